// round 11
// baseline (speedup 1.0000x reference)
#include <cuda_runtime.h>
#include <math.h>

// ---------------------------------------------------------------------------
// StructureLayer (IPA) — B=1, N=512, H=12, C_S=384, C_P=128, C_H=16,
// P_QK=4, P_V=8.  Output: [ s2 (512*384) | rot_new (512*9) | trans_new (512*3) ]
// ---------------------------------------------------------------------------

#define NN 512
#define CS 384
#define CP 128
#define HDS 12

// proj row layout: [ q(192) | kv(384) | qp(144) | kvp(432) ]  = 1152
#define LDP 1152
#define OFF_Q   0
#define OFF_KV  192
#define OFF_QP  576
#define OFF_KVP 720

#define SQK 0.14433756729740643f    // sqrt(1/48)
#define SB  0.5773502691896258f     // sqrt(1/3)
#define SHW 0.13608276348795434f    // sqrt(1/54)

// opair_tc dynamic smem: As 512*17 u32 + Bs 64*132 u32
#define OPAIR_SMEM ((512 * 17 + 64 * 132) * 4)
// bias_tc dynamic smem: As 64*132 u32 + Bs 128*40 u32
#define BIAS_SMEM ((64 * 132 + 128 * 40) * 4)

// ---- scratch (device globals) ----------------------------------------------
__device__ float g_wcat[CS * LDP];
__device__ float g_bcat[LDP];
__device__ float g_proj[NN * LDP];       // only q / qp sections used
__device__ float g_ppart[2 * NN * LDP];  // proj split-K partials
__device__ float g_kpack[HDS * NN * 16];
__device__ float g_kppack[HDS * NN * 12];
__device__ float g_vpack[HDS * NN * 64]; // [h][j][ v(16) | vp(24) | pad=0 ]
__device__ float g_att[HDS * NN * NN];   // bias planes, then probs [h][i][j]
__device__ float g_cat[NN * 2112];
__device__ float g_part[3 * NN * CS];    // split-K partials (A)
__device__ float g_partB[3 * NN * CS];   // split-K partials (B)
__device__ float g_x2[NN * CS];

// ---------------------------------------------------------------------------
// tf32 helpers
// ---------------------------------------------------------------------------
__device__ __forceinline__ unsigned cvt_tf32(float x)
{
    unsigned r;
    asm("cvt.rna.tf32.f32 %0, %1;" : "=r"(r) : "f"(x));
    return r;
}

__device__ __forceinline__ void mma_tf32(float* d, const unsigned* a,
                                         const unsigned* b)
{
    asm volatile(
        "mma.sync.aligned.m16n8k8.row.col.f32.tf32.tf32.f32 "
        "{%0,%1,%2,%3}, {%4,%5,%6,%7}, {%8,%9}, {%0,%1,%2,%3};\n"
        : "+f"(d[0]), "+f"(d[1]), "+f"(d[2]), "+f"(d[3])
        : "r"(a[0]), "r"(a[1]), "r"(a[2]), "r"(a[3]),
          "r"(b[0]), "r"(b[1]));
}

// A-load: optionally reduce 3 split-K partials + bias + relu on the fly.
__device__ __forceinline__ float4 ldA4(const float* p,
                                       const float* abias, int bcol,
                                       long long SP, int arelu)
{
    float4 v = *(const float4*)p;
    if (abias) {
        float4 v1 = *(const float4*)(p + SP);
        float4 v2 = *(const float4*)(p + 2 * SP);
        float4 bb = *(const float4*)(abias + bcol);
        v.x += v1.x + v2.x + bb.x;
        v.y += v1.y + v2.y + bb.y;
        v.z += v1.z + v2.z + bb.z;
        v.w += v1.w + v2.w + bb.w;
        if (arelu) {
            v.x = fmaxf(v.x, 0.f); v.y = fmaxf(v.y, 0.f);
            v.z = fmaxf(v.z, 0.f); v.w = fmaxf(v.w, 0.f);
        }
    }
    return v;
}

// ---------------------------------------------------------------------------
// Pack projection weights/biases into one (384 x 1152) matrix. float4 copies.
// ---------------------------------------------------------------------------
__global__ void pack_w_kernel(const float* __restrict__ w_q,  const float* __restrict__ b_q,
                              const float* __restrict__ w_kv, const float* __restrict__ b_kv,
                              const float* __restrict__ w_qp, const float* __restrict__ b_qp,
                              const float* __restrict__ w_kvp,const float* __restrict__ b_kvp,
                              float* __restrict__ wcat, float* __restrict__ bcat)
{
    const int NW4 = CS * LDP / 4;
    int idx = blockIdx.x * blockDim.x + threadIdx.x;
    if (idx < NW4) {
        int r = idx / (LDP / 4), c = (idx % (LDP / 4)) * 4;
        float4 v;
        if      (c < 192) v = *(const float4*)(w_q  + r * 192 + c);
        else if (c < 576) v = *(const float4*)(w_kv + r * 384 + (c - 192));
        else if (c < 720) v = *(const float4*)(w_qp + r * 144 + (c - 576));
        else              v = *(const float4*)(w_kvp + r * 432 + (c - 720));
        *(float4*)(wcat + r * LDP + c) = v;
    } else if (idx < NW4 + LDP / 4) {
        int c = (idx - NW4) * 4;
        float4 v;
        if      (c < 192) v = *(const float4*)(b_q  + c);
        else if (c < 576) v = *(const float4*)(b_kv + (c - 192));
        else if (c < 720) v = *(const float4*)(b_qp + (c - 576));
        else              v = *(const float4*)(b_kvp + (c - 720));
        *(float4*)(bcat + c) = v;
    }
}

// ---------------------------------------------------------------------------
// tf32 tensor-core GEMM: 64x64 tile, 128 threads, double-buffered smem.
// z = zb*KS + zk (batch x split-K).  Optional fused A-side 3-partial
// reduce + bias + relu (abias != nullptr).
// ---------------------------------------------------------------------------
__global__ void __launch_bounds__(128)
gemm64_kernel(const float* __restrict__ A, int lda, long long sAz, long long sAk,
              const float* __restrict__ B, int ldb, long long sBz, long long sBk,
              const float* __restrict__ bias,
              float* __restrict__ C, int ldc, long long sCz, long long sCk,
              int K, int KS,
              const float* __restrict__ abias, long long aSP, int aKoff, int arelu)
{
    const int zb = blockIdx.z / KS, zk = blockIdx.z % KS;
    A += (size_t)zb * (size_t)sAz + (size_t)zk * (size_t)sAk;
    B += (size_t)zb * (size_t)sBz + (size_t)zk * (size_t)sBk;
    C += (size_t)zb * (size_t)sCz + (size_t)zk * (size_t)sCk;
    const int azoff = zk * aKoff;

    __shared__ __align__(16) unsigned As[2][16][72];
    __shared__ __align__(16) unsigned Bs[2][16][72];

    const int bm = blockIdx.y * 64, bn = blockIdx.x * 64;
    const int tid = threadIdx.x;
    const int lane = tid & 31, warp = tid >> 5;
    const int g = lane >> 2, t4 = lane & 3;
    const int wm = (warp >> 1) * 32, wn = (warp & 1) * 32;

    const int ar = tid >> 2, ak = (tid & 3) * 4;
    const int br = tid >> 4, bc = (tid & 15) * 4;

    const float* Ab = A + (size_t)bm * lda;

    float4 ra0, ra1, rb0, rb1;
    ra0 = ldA4(Ab + (size_t)ar * lda + ak, abias, azoff + ak, aSP, arelu);
    ra1 = ldA4(Ab + (size_t)(ar + 32) * lda + ak, abias, azoff + ak, aSP, arelu);
    rb0 = *(const float4*)(B + (size_t)br * ldb + bn + bc);
    rb1 = *(const float4*)(B + (size_t)(br + 8) * ldb + bn + bc);

    As[0][ak+0][ar] = cvt_tf32(ra0.x); As[0][ak+1][ar] = cvt_tf32(ra0.y);
    As[0][ak+2][ar] = cvt_tf32(ra0.z); As[0][ak+3][ar] = cvt_tf32(ra0.w);
    As[0][ak+0][ar+32] = cvt_tf32(ra1.x); As[0][ak+1][ar+32] = cvt_tf32(ra1.y);
    As[0][ak+2][ar+32] = cvt_tf32(ra1.z); As[0][ak+3][ar+32] = cvt_tf32(ra1.w);
    {
        uint4 u0 = make_uint4(cvt_tf32(rb0.x), cvt_tf32(rb0.y),
                              cvt_tf32(rb0.z), cvt_tf32(rb0.w));
        uint4 u1 = make_uint4(cvt_tf32(rb1.x), cvt_tf32(rb1.y),
                              cvt_tf32(rb1.z), cvt_tf32(rb1.w));
        *(uint4*)&Bs[0][br][bc]     = u0;
        *(uint4*)&Bs[0][br + 8][bc] = u1;
    }
    __syncthreads();

    float acc[2][4][4];
    #pragma unroll
    for (int mt = 0; mt < 2; mt++)
        #pragma unroll
        for (int nt = 0; nt < 4; nt++)
            #pragma unroll
            for (int r = 0; r < 4; r++) acc[mt][nt][r] = 0.f;

    int buf = 0;
    for (int k0 = 0; k0 < K; k0 += 16) {
        const bool more = (k0 + 16) < K;
        if (more) {
            int kc = k0 + 16 + ak;
            ra0 = ldA4(Ab + (size_t)ar * lda + kc, abias, azoff + kc, aSP, arelu);
            ra1 = ldA4(Ab + (size_t)(ar + 32) * lda + kc, abias, azoff + kc, aSP, arelu);
            rb0 = *(const float4*)(B + (size_t)(k0 + 16 + br) * ldb + bn + bc);
            rb1 = *(const float4*)(B + (size_t)(k0 + 16 + br + 8) * ldb + bn + bc);
        }
        #pragma unroll
        for (int kk = 0; kk < 16; kk += 8) {
            unsigned af[2][4], bf[4][2];
            #pragma unroll
            for (int mt = 0; mt < 2; mt++) {
                int m0 = wm + mt * 16 + g;
                af[mt][0] = As[buf][kk + t4][m0];
                af[mt][1] = As[buf][kk + t4][m0 + 8];
                af[mt][2] = As[buf][kk + 4 + t4][m0];
                af[mt][3] = As[buf][kk + 4 + t4][m0 + 8];
            }
            #pragma unroll
            for (int nt = 0; nt < 4; nt++) {
                int n0 = wn + nt * 8 + g;
                bf[nt][0] = Bs[buf][kk + t4][n0];
                bf[nt][1] = Bs[buf][kk + 4 + t4][n0];
            }
            #pragma unroll
            for (int mt = 0; mt < 2; mt++)
                #pragma unroll
                for (int nt = 0; nt < 4; nt++)
                    mma_tf32(acc[mt][nt], af[mt], bf[nt]);
        }
        if (more) {
            buf ^= 1;
            __syncthreads();
            As[buf][ak+0][ar] = cvt_tf32(ra0.x); As[buf][ak+1][ar] = cvt_tf32(ra0.y);
            As[buf][ak+2][ar] = cvt_tf32(ra0.z); As[buf][ak+3][ar] = cvt_tf32(ra0.w);
            As[buf][ak+0][ar+32] = cvt_tf32(ra1.x); As[buf][ak+1][ar+32] = cvt_tf32(ra1.y);
            As[buf][ak+2][ar+32] = cvt_tf32(ra1.z); As[buf][ak+3][ar+32] = cvt_tf32(ra1.w);
            uint4 u0 = make_uint4(cvt_tf32(rb0.x), cvt_tf32(rb0.y),
                                  cvt_tf32(rb0.z), cvt_tf32(rb0.w));
            uint4 u1 = make_uint4(cvt_tf32(rb1.x), cvt_tf32(rb1.y),
                                  cvt_tf32(rb1.z), cvt_tf32(rb1.w));
            *(uint4*)&Bs[buf][br][bc]     = u0;
            *(uint4*)&Bs[buf][br + 8][bc] = u1;
            __syncthreads();
        }
    }

    #pragma unroll
    for (int mt = 0; mt < 2; mt++) {
        int row0 = bm + wm + mt * 16 + g;
        #pragma unroll
        for (int nt = 0; nt < 4; nt++) {
            int col = bn + wn + nt * 8 + t4 * 2;
            float b0 = 0.f, b1 = 0.f;
            if (bias) { b0 = bias[col]; b1 = bias[col + 1]; }
            float2 v0 = make_float2(acc[mt][nt][0] + b0, acc[mt][nt][1] + b1);
            float2 v1 = make_float2(acc[mt][nt][2] + b0, acc[mt][nt][3] + b1);
            *(float2*)(C + (size_t)row0 * ldc + col)       = v0;
            *(float2*)(C + (size_t)(row0 + 8) * ldc + col) = v1;
        }
    }
}

// ---------------------------------------------------------------------------
// Tensor-core bias kernel:  att[h][ij] = (p[ij,:]·w_b[:,h] + b_b[h]) * SB
// One block = 64 ij-rows.  A = p tile [m=64][k=128] (stride 132, bank-free),
// B = w_b [k=128][n=16 padded] (stride 40).  One-shot staging, 16 k8 steps.
// ---------------------------------------------------------------------------
extern __shared__ unsigned bias_smem[];
__global__ void __launch_bounds__(128)
bias_tc_kernel(const float* __restrict__ p,
               const float* __restrict__ w_b,
               const float* __restrict__ b_b,
               float* __restrict__ att)
{
    unsigned* As = bias_smem;               // [64][132]
    unsigned* Bs = bias_smem + 64 * 132;    // [128][40]
    __shared__ float bbs[16];

    const int tid = threadIdx.x;
    const long long row0 = (long long)blockIdx.x * 64;

    // stage w_b -> Bs[k][n]
    for (int e = tid; e < 128 * 16; e += 128) {
        int k = e >> 4, n = e & 15;
        float v = (n < 12) ? w_b[k * HDS + n] : 0.f;
        Bs[k * 40 + n] = cvt_tf32(v);
    }
    if (tid < 16) bbs[tid] = (tid < 12) ? b_b[tid] : 0.f;

    // stage p tile -> As[m][k]  (coalesced float4 loads)
    const int ar = tid >> 2, ak = (tid & 3) * 4;
    const float* Ab = p + row0 * CP;
    #pragma unroll
    for (int ko = 0; ko < 128; ko += 16) {
        float4 r0 = *(const float4*)(Ab + (size_t)ar * CP + ko + ak);
        float4 r1 = *(const float4*)(Ab + (size_t)(ar + 32) * CP + ko + ak);
        uint4 u0 = make_uint4(cvt_tf32(r0.x), cvt_tf32(r0.y),
                              cvt_tf32(r0.z), cvt_tf32(r0.w));
        uint4 u1 = make_uint4(cvt_tf32(r1.x), cvt_tf32(r1.y),
                              cvt_tf32(r1.z), cvt_tf32(r1.w));
        *(uint4*)&As[ar * 132 + ko + ak]        = u0;
        *(uint4*)&As[(ar + 32) * 132 + ko + ak] = u1;
    }
    __syncthreads();

    const int lane = tid & 31, warp = tid >> 5;
    const int g = lane >> 2, t4 = lane & 3;
    const int m0 = warp * 16;

    float acc[2][4];
    #pragma unroll
    for (int nt = 0; nt < 2; nt++)
        #pragma unroll
        for (int r = 0; r < 4; r++) acc[nt][r] = 0.f;

    #pragma unroll
    for (int kk = 0; kk < 128; kk += 8) {
        unsigned af[4];
        af[0] = As[(m0 + g) * 132 + kk + t4];
        af[1] = As[(m0 + g + 8) * 132 + kk + t4];
        af[2] = As[(m0 + g) * 132 + kk + 4 + t4];
        af[3] = As[(m0 + g + 8) * 132 + kk + 4 + t4];
        #pragma unroll
        for (int nt = 0; nt < 2; nt++) {
            unsigned bf[2];
            int n0 = nt * 8 + g;
            bf[0] = Bs[(kk + t4) * 40 + n0];
            bf[1] = Bs[(kk + 4 + t4) * 40 + n0];
            mma_tf32(acc[nt], af, bf);
        }
    }

    const long long PLANE = (long long)NN * NN;
    #pragma unroll
    for (int nt = 0; nt < 2; nt++) {
        #pragma unroll
        for (int dh = 0; dh < 2; dh++) {
            int h = nt * 8 + t4 * 2 + dh;
            if (h < HDS) {
                float bb = bbs[h];
                att[(size_t)h * PLANE + row0 + m0 + g] =
                    (acc[nt][dh] + bb) * SB;
                att[(size_t)h * PLANE + row0 + m0 + g + 8] =
                    (acc[nt][2 + dh] + bb) * SB;
            }
        }
    }
}

// ---------------------------------------------------------------------------
// ov GEMM (att @ [v|vp], per-head) with fused postproc epilogue:
// writes o / rotated-op / norms directly into cat.  grid (1, 8, HDS).
// ---------------------------------------------------------------------------
__global__ void __launch_bounds__(128)
ovgemm_kernel(const float* __restrict__ att,
              const float* __restrict__ vpk,
              const float* __restrict__ rot,
              const float* __restrict__ trans,
              float* __restrict__ cat)
{
    const int h = blockIdx.z;
    const float* A = att + (size_t)h * NN * NN;
    const float* B = vpk + (size_t)h * NN * 64;

    __shared__ __align__(16) unsigned As[2][16][72];
    __shared__ __align__(16) unsigned Bs[2][16][72];
    __shared__ float sm[64][41];

    const int bm = blockIdx.y * 64;
    const int tid = threadIdx.x;
    const int lane = tid & 31, warp = tid >> 5;
    const int g = lane >> 2, t4 = lane & 3;
    const int wm = (warp >> 1) * 32, wn = (warp & 1) * 32;

    const int ar = tid >> 2, ak = (tid & 3) * 4;
    const int br = tid >> 4, bc = (tid & 15) * 4;

    const float* Ab = A + (size_t)bm * NN;

    float4 ra0, ra1, rb0, rb1;
    ra0 = *(const float4*)(Ab + (size_t)ar * NN + ak);
    ra1 = *(const float4*)(Ab + (size_t)(ar + 32) * NN + ak);
    rb0 = *(const float4*)(B + (size_t)br * 64 + bc);
    rb1 = *(const float4*)(B + (size_t)(br + 8) * 64 + bc);

    As[0][ak+0][ar] = cvt_tf32(ra0.x); As[0][ak+1][ar] = cvt_tf32(ra0.y);
    As[0][ak+2][ar] = cvt_tf32(ra0.z); As[0][ak+3][ar] = cvt_tf32(ra0.w);
    As[0][ak+0][ar+32] = cvt_tf32(ra1.x); As[0][ak+1][ar+32] = cvt_tf32(ra1.y);
    As[0][ak+2][ar+32] = cvt_tf32(ra1.z); As[0][ak+3][ar+32] = cvt_tf32(ra1.w);
    {
        uint4 u0 = make_uint4(cvt_tf32(rb0.x), cvt_tf32(rb0.y),
                              cvt_tf32(rb0.z), cvt_tf32(rb0.w));
        uint4 u1 = make_uint4(cvt_tf32(rb1.x), cvt_tf32(rb1.y),
                              cvt_tf32(rb1.z), cvt_tf32(rb1.w));
        *(uint4*)&Bs[0][br][bc]     = u0;
        *(uint4*)&Bs[0][br + 8][bc] = u1;
    }
    __syncthreads();

    float acc[2][4][4];
    #pragma unroll
    for (int mt = 0; mt < 2; mt++)
        #pragma unroll
        for (int nt = 0; nt < 4; nt++)
            #pragma unroll
            for (int r = 0; r < 4; r++) acc[mt][nt][r] = 0.f;

    int buf = 0;
    for (int k0 = 0; k0 < NN; k0 += 16) {
        const bool more = (k0 + 16) < NN;
        if (more) {
            ra0 = *(const float4*)(Ab + (size_t)ar * NN + k0 + 16 + ak);
            ra1 = *(const float4*)(Ab + (size_t)(ar + 32) * NN + k0 + 16 + ak);
            rb0 = *(const float4*)(B + (size_t)(k0 + 16 + br) * 64 + bc);
            rb1 = *(const float4*)(B + (size_t)(k0 + 16 + br + 8) * 64 + bc);
        }
        #pragma unroll
        for (int kk = 0; kk < 16; kk += 8) {
            unsigned af[2][4], bf[4][2];
            #pragma unroll
            for (int mt = 0; mt < 2; mt++) {
                int m0 = wm + mt * 16 + g;
                af[mt][0] = As[buf][kk + t4][m0];
                af[mt][1] = As[buf][kk + t4][m0 + 8];
                af[mt][2] = As[buf][kk + 4 + t4][m0];
                af[mt][3] = As[buf][kk + 4 + t4][m0 + 8];
            }
            #pragma unroll
            for (int nt = 0; nt < 4; nt++) {
                int n0 = wn + nt * 8 + g;
                bf[nt][0] = Bs[buf][kk + t4][n0];
                bf[nt][1] = Bs[buf][kk + 4 + t4][n0];
            }
            #pragma unroll
            for (int mt = 0; mt < 2; mt++)
                #pragma unroll
                for (int nt = 0; nt < 4; nt++)
                    mma_tf32(acc[mt][nt], af[mt], bf[nt]);
        }
        if (more) {
            buf ^= 1;
            __syncthreads();
            As[buf][ak+0][ar] = cvt_tf32(ra0.x); As[buf][ak+1][ar] = cvt_tf32(ra0.y);
            As[buf][ak+2][ar] = cvt_tf32(ra0.z); As[buf][ak+3][ar] = cvt_tf32(ra0.w);
            As[buf][ak+0][ar+32] = cvt_tf32(ra1.x); As[buf][ak+1][ar+32] = cvt_tf32(ra1.y);
            As[buf][ak+2][ar+32] = cvt_tf32(ra1.z); As[buf][ak+3][ar+32] = cvt_tf32(ra1.w);
            uint4 u0 = make_uint4(cvt_tf32(rb0.x), cvt_tf32(rb0.y),
                                  cvt_tf32(rb0.z), cvt_tf32(rb0.w));
            uint4 u1 = make_uint4(cvt_tf32(rb1.x), cvt_tf32(rb1.y),
                                  cvt_tf32(rb1.z), cvt_tf32(rb1.w));
            *(uint4*)&Bs[buf][br][bc]     = u0;
            *(uint4*)&Bs[buf][br + 8][bc] = u1;
            __syncthreads();
        }
    }

    #pragma unroll
    for (int mt = 0; mt < 2; mt++) {
        int r0 = wm + mt * 16 + g;
        #pragma unroll
        for (int nt = 0; nt < 4; nt++) {
            int col = wn + nt * 8 + t4 * 2;
            if (col < 40) {
                sm[r0][col]       = acc[mt][nt][0];
                sm[r0][col + 1]   = acc[mt][nt][1];
                sm[r0 + 8][col]     = acc[mt][nt][2];
                sm[r0 + 8][col + 1] = acc[mt][nt][3];
            }
        }
    }
    __syncthreads();

    #pragma unroll
    for (int l = 0; l < 8; l++) {
        int e = tid + l * 128;
        int r = e >> 4, c = e & 15;
        cat[(size_t)(bm + r) * 2112 + h * 16 + c] = sm[r][c];
    }
    #pragma unroll
    for (int l = 0; l < 4; l++) {
        int e = tid + l * 128;
        int r = e >> 3, pp = e & 7;
        int i = bm + r;
        float vx = sm[r][16 + pp*3 + 0] - trans[i*3 + 0];
        float vy = sm[r][16 + pp*3 + 1] - trans[i*3 + 1];
        float vz = sm[r][16 + pp*3 + 2] - trans[i*3 + 2];
        const float* R = rot + i * 9;
        float ox = R[0]*vx + R[3]*vy + R[6]*vz;
        float oy = R[1]*vx + R[4]*vy + R[7]*vz;
        float oz = R[2]*vx + R[5]*vy + R[8]*vz;
        float* ci = cat + (size_t)i * 2112;
        ci[192 + h*24 + pp*3 + 0] = ox;
        ci[192 + h*24 + pp*3 + 1] = oy;
        ci[192 + h*24 + pp*3 + 2] = oz;
        ci[480 + h*8 + pp] = sqrtf(ox*ox + oy*oy + oz*oz + 1e-8f);
    }
}

// ---------------------------------------------------------------------------
// o_pair via tensor cores: per-i block computes (16x512)@(512x128)
// ---------------------------------------------------------------------------
extern __shared__ unsigned opair_smem[];
__global__ void __launch_bounds__(128)
opair_tc_kernel(const float* __restrict__ att,
                const float* __restrict__ p,
                float* __restrict__ cat)
{
    const int i = blockIdx.x;
    unsigned* As = opair_smem;                 // [j][h] stride 17
    unsigned* Bs = opair_smem + 512 * 17;      // [jj][c] stride 132
    const int tid = threadIdx.x;

    for (int idx = tid; idx < HDS * NN; idx += 128) {
        int j = idx & 511, h = idx >> 9;
        As[j * 17 + h] = cvt_tf32(att[((size_t)(h * NN) + i) * NN + j]);
    }
    for (int idx = tid; idx < 4 * NN; idx += 128) {
        int j = idx & 511, h = 12 + (idx >> 9);
        As[j * 17 + h] = 0u;
    }

    const int lane = tid & 31, warp = tid >> 5;
    const int g = lane >> 2, t4 = lane & 3;
    const int wn = warp * 32;

    float acc[4][4];
    #pragma unroll
    for (int nt = 0; nt < 4; nt++)
        #pragma unroll
        for (int r = 0; r < 4; r++) acc[nt][r] = 0.f;

    const float4* pi4 = (const float4*)(p + (size_t)i * NN * CP);

    for (int j0 = 0; j0 < NN; j0 += 64) {
        __syncthreads();
        #pragma unroll
        for (int l = 0; l < 16; l++) {
            int e = tid + l * 128;
            int jj = e >> 5, c4 = e & 31;
            float4 v = pi4[(size_t)(j0 + jj) * 32 + c4];
            uint4 u = make_uint4(cvt_tf32(v.x), cvt_tf32(v.y),
                                 cvt_tf32(v.z), cvt_tf32(v.w));
            *(uint4*)&Bs[jj * 132 + c4 * 4] = u;
        }
        __syncthreads();
        #pragma unroll
        for (int ks = 0; ks < 8; ks++) {
            unsigned af[4];
            int kg = (j0 + ks * 8 + t4) * 17;
            int kg4 = (j0 + ks * 8 + 4 + t4) * 17;
            af[0] = As[kg + g];
            af[1] = As[kg + g + 8];
            af[2] = As[kg4 + g];
            af[3] = As[kg4 + g + 8];
            #pragma unroll
            for (int nt = 0; nt < 4; nt++) {
                unsigned bf[2];
                int n0 = wn + nt * 8 + g;
                bf[0] = Bs[(ks * 8 + t4) * 132 + n0];
                bf[1] = Bs[(ks * 8 + 4 + t4) * 132 + n0];
                mma_tf32(acc[nt], af, bf);
            }
        }
    }

    float* dst = cat + (size_t)i * 2112 + 576;
    #pragma unroll
    for (int nt = 0; nt < 4; nt++) {
        int col = wn + nt * 8 + t4 * 2;
        dst[g * 128 + col]     = acc[nt][0];
        dst[g * 128 + col + 1] = acc[nt][1];
        if (g + 8 < HDS) {
            dst[(g + 8) * 128 + col]     = acc[nt][2];
            dst[(g + 8) * 128 + col + 1] = acc[nt][3];
        }
    }
}

// ---------------------------------------------------------------------------
// Fused proj split-K reduce + bias + rotate + repack.
// ---------------------------------------------------------------------------
__global__ void rotpack_kernel(const float* __restrict__ ppart,
                               const float* __restrict__ bcat,
                               const float* __restrict__ rot,
                               const float* __restrict__ trans,
                               float* __restrict__ proj,
                               float* __restrict__ kpack,
                               float* __restrict__ kppack,
                               float* __restrict__ vpack)
{
    const long long SP = (long long)NN * LDP;
    const int S0 = NN * 48;
    const int S1 = S0 + HDS * NN * 4;
    const int S2 = S1 + HDS * NN * 4;
    const int S3 = S2 + HDS * NN * 4;
    const int S4 = S3 + HDS * NN * 8;
    const int S5 = S4 + NN * 48;
    int idx = blockIdx.x * blockDim.x + threadIdx.x;

    if (idx < S0) {
        int j = idx / 48, c = (idx % 48) * 4;
        const float* p0 = ppart + (size_t)j * LDP + c;
        float4 a = *(const float4*)p0;
        float4 b = *(const float4*)(p0 + SP);
        float4 bb = *(const float4*)(bcat + c);
        *(float4*)(proj + (size_t)j * LDP + c) =
            make_float4(a.x+b.x+bb.x, a.y+b.y+bb.y, a.z+b.z+bb.z, a.w+b.w+bb.w);
    } else if (idx < S1) {
        int t = idx - S0;
        int c = (t & 3) * 4, j = (t >> 2) & 511, h = t >> 11;
        int col = OFF_KV + h * 32 + c;
        const float* p0 = ppart + (size_t)j * LDP + col;
        float4 a = *(const float4*)p0;
        float4 b = *(const float4*)(p0 + SP);
        float4 bb = *(const float4*)(bcat + col);
        *(float4*)(kpack + (((size_t)h * NN) + j) * 16 + c) =
            make_float4(a.x+b.x+bb.x, a.y+b.y+bb.y, a.z+b.z+bb.z, a.w+b.w+bb.w);
    } else if (idx < S2) {
        int t = idx - S1;
        int c = (t & 3) * 4, j = (t >> 2) & 511, h = t >> 11;
        int col = OFF_KV + h * 32 + 16 + c;
        const float* p0 = ppart + (size_t)j * LDP + col;
        float4 a = *(const float4*)p0;
        float4 b = *(const float4*)(p0 + SP);
        float4 bb = *(const float4*)(bcat + col);
        *(float4*)(vpack + (((size_t)h * NN) + j) * 64 + c) =
            make_float4(a.x+b.x+bb.x, a.y+b.y+bb.y, a.z+b.z+bb.z, a.w+b.w+bb.w);
    } else if (idx < S4) {
        int t = idx - S2;
        int pp, j, h;
        float* dst;
        if (t < HDS * NN * 4) {
            pp = t & 3; j = (t >> 2) & 511; h = t >> 11;
            dst = kppack + (((size_t)h * NN) + j) * 12 + pp * 3;
        } else {
            t -= HDS * NN * 4;
            int vp = t & 7; j = (t >> 3) & 511; h = t >> 12;
            pp = 4 + vp;
            dst = vpack + (((size_t)h * NN) + j) * 64 + 16 + vp * 3;
        }
        int col = OFF_KVP + h * 36 + pp * 3;
        const float* p0 = ppart + (size_t)j * LDP + col;
        float x = p0[0] + p0[SP + 0] + bcat[col + 0];
        float y = p0[1] + p0[SP + 1] + bcat[col + 1];
        float z = p0[2] + p0[SP + 2] + bcat[col + 2];
        const float* R = rot + j * 9;
        const float* tr = trans + j * 3;
        dst[0] = R[0]*x + R[1]*y + R[2]*z + tr[0];
        dst[1] = R[3]*x + R[4]*y + R[5]*z + tr[1];
        dst[2] = R[6]*x + R[7]*y + R[8]*z + tr[2];
    } else if (idx < S5) {
        int t = idx - S4;
        int pt = t % 48, j = t / 48;
        int col = OFF_QP + pt * 3;
        const float* p0 = ppart + (size_t)j * LDP + col;
        float x = p0[0] + p0[SP + 0] + bcat[col + 0];
        float y = p0[1] + p0[SP + 1] + bcat[col + 1];
        float z = p0[2] + p0[SP + 2] + bcat[col + 2];
        const float* R = rot + j * 9;
        const float* tr = trans + j * 3;
        float* pv = proj + (size_t)j * LDP + col;
        pv[0] = R[0]*x + R[1]*y + R[2]*z + tr[0];
        pv[1] = R[3]*x + R[4]*y + R[5]*z + tr[1];
        pv[2] = R[6]*x + R[7]*y + R[8]*z + tr[2];
    }
}

// ---------------------------------------------------------------------------
// Fused logits + softmax.  Block = (i-tile of 8, head h).  256 threads.
// ---------------------------------------------------------------------------
__global__ void logits_softmax_kernel(const float* __restrict__ proj,
                                      const float* __restrict__ kpack,
                                      const float* __restrict__ kppack,
                                      const float* __restrict__ mask,
                                      const float* __restrict__ head_w,
                                      float* __restrict__ att)
{
    const int i0 = blockIdx.x * 8, h = blockIdx.y;
    const int tid = threadIdx.x;

    __shared__ float att_s[8][NN];
    __shared__ float kt[64][17];
    __shared__ float kpt[64][13];
    __shared__ float q_s[8][17];
    __shared__ float qp_s[8][13];
    __shared__ float m_i[8];
    __shared__ float sh_hw;

    if (tid < 128) {
        int il = tid >> 4, c = tid & 15;
        q_s[il][c] = proj[(size_t)(i0 + il) * LDP + OFF_Q + h * 16 + c];
    } else if (tid < 224) {
        int e = tid - 128;
        int il = e / 12, c = e % 12;
        qp_s[il][c] = proj[(size_t)(i0 + il) * LDP + OFF_QP + h * 12 + c];
    } else if (tid < 232) {
        m_i[tid - 224] = mask[i0 + (tid - 224)];
    } else if (tid == 232) {
        float w = head_w[h];
        float sp = fmaxf(w, 0.f) + log1pf(expf(-fabsf(w)));
        sh_hw = sp * SHW;
    }

    const float* kb  = kpack  + (size_t)(h * NN) * 16;
    const float* kpb = kppack + (size_t)(h * NN) * 12;

    const int jl = tid & 63, ig = tid >> 6;

    for (int j0 = 0; j0 < NN; j0 += 64) {
        #pragma unroll
        for (int k = 0; k < 4; k++) {
            int e = tid + k * 256;
            int r = e >> 4, c = e & 15;
            kt[r][c] = kb[(size_t)(j0 + r) * 16 + c];
        }
        #pragma unroll
        for (int k = 0; k < 3; k++) {
            int e = tid + k * 256;
            if (e < 768) {
                int r = e / 12, c = e % 12;
                kpt[r][c] = kpb[(size_t)(j0 + r) * 12 + c];
            }
        }
        __syncthreads();

        float mj = mask[j0 + jl];
        float hw = sh_hw;
        #pragma unroll
        for (int ii = 0; ii < 2; ii++) {
            int il = ig * 2 + ii;
            float qk = 0.f;
            #pragma unroll
            for (int c = 0; c < 16; c++) qk = fmaf(q_s[il][c], kt[jl][c], qk);
            float d2 = 0.f;
            #pragma unroll
            for (int d = 0; d < 12; d++) {
                float dd = qp_s[il][d] - kpt[jl][d];
                d2 = fmaf(dd, dd, d2);
            }
            float bias = att[((size_t)(h * NN) + i0 + il) * NN + j0 + jl];
            att_s[il][j0 + jl] = qk * SQK + bias - 0.5f * hw * d2
                               + (m_i[il] * mj - 1.0f) * 100000.0f;
        }
        __syncthreads();
    }

    const int w = tid >> 5, lane = tid & 31;
    float vals[16];
    float vmax = -1e30f;
    #pragma unroll
    for (int k = 0; k < 16; k++) {
        vals[k] = att_s[w][lane + 32 * k];
        vmax = fmaxf(vmax, vals[k]);
    }
    #pragma unroll
    for (int o = 16; o > 0; o >>= 1)
        vmax = fmaxf(vmax, __shfl_xor_sync(0xffffffffu, vmax, o));
    float sum = 0.f;
    #pragma unroll
    for (int k = 0; k < 16; k++) { vals[k] = expf(vals[k] - vmax); sum += vals[k]; }
    #pragma unroll
    for (int o = 16; o > 0; o >>= 1)
        sum += __shfl_xor_sync(0xffffffffu, sum, o);
    float inv = 1.0f / sum;
    float* arow = att + ((size_t)(h * NN) + i0 + w) * NN;
    #pragma unroll
    for (int k = 0; k < 16; k++)
        arow[lane + 32 * k] = vals[k] * inv;
}

// ---------------------------------------------------------------------------
// 3-way split-K reduce + bias + residual + LayerNorm.  Block/row, 128 thr.
// ---------------------------------------------------------------------------
__global__ void reduce_ln_kernel(const float* __restrict__ part,
                                 const float* __restrict__ bias,
                                 const float* __restrict__ res,
                                 const float* __restrict__ g,
                                 const float* __restrict__ b,
                                 float* __restrict__ y)
{
    __shared__ float rs[128], rs2[128];
    const int i = blockIdx.x, tid = threadIdx.x;
    const size_t SP = (size_t)NN * CS;
    float v[3];
    float sm = 0.f, sm2 = 0.f;
    #pragma unroll
    for (int k = 0; k < 3; k++) {
        int c = tid + k * 128;
        size_t o = (size_t)i * CS + c;
        float x = part[o] + part[SP + o] + part[2*SP + o] + bias[c] + res[o];
        v[k] = x;
        sm += x; sm2 += x * x;
    }
    rs[tid] = sm; rs2[tid] = sm2;
    __syncthreads();
    for (int st = 64; st > 0; st >>= 1) {
        if (tid < st) { rs[tid] += rs[tid + st]; rs2[tid] += rs2[tid + st]; }
        __syncthreads();
    }
    float mean = rs[0] * (1.0f / CS);
    float var  = rs2[0] * (1.0f / CS) - mean * mean;
    float inv  = rsqrtf(var + 1e-5f);
    #pragma unroll
    for (int k = 0; k < 3; k++) {
        int c = tid + k * 128;
        y[(size_t)i * CS + c] = (v[k] - mean) * inv * g[c] + b[c];
    }
}

// ---------------------------------------------------------------------------
// Fused: 3-way reduce + bias + residual + LayerNorm2 + backbone projection
// + quaternion frame update.  Block per row, 128 threads.
// ---------------------------------------------------------------------------
__global__ void lnbb_kernel(const float* __restrict__ part,
                            const float* __restrict__ bias,
                            const float* __restrict__ res,
                            const float* __restrict__ g,
                            const float* __restrict__ b,
                            const float* __restrict__ bb_w,
                            const float* __restrict__ bb_b,
                            const float* __restrict__ rot,
                            const float* __restrict__ trans,
                            float* __restrict__ out)
{
    __shared__ float rs[128], rs2[128], ys[CS], wsm[CS * 6], u[6];
    const int i = blockIdx.x, tid = threadIdx.x;
    const size_t SP = (size_t)NN * CS;

    #pragma unroll
    for (int k = 0; k < 18; k++) wsm[tid + k * 128] = bb_w[tid + k * 128];

    float v[3];
    float sm = 0.f, sm2 = 0.f;
    #pragma unroll
    for (int k = 0; k < 3; k++) {
        int c = tid + k * 128;
        size_t o = (size_t)i * CS + c;
        float x = part[o] + part[SP + o] + part[2*SP + o] + bias[c] + res[o];
        v[k] = x;
        sm += x; sm2 += x * x;
    }
    rs[tid] = sm; rs2[tid] = sm2;
    __syncthreads();
    for (int st = 64; st > 0; st >>= 1) {
        if (tid < st) { rs[tid] += rs[tid + st]; rs2[tid] += rs2[tid + st]; }
        __syncthreads();
    }
    float mean = rs[0] * (1.0f / CS);
    float var  = rs2[0] * (1.0f / CS) - mean * mean;
    float inv  = rsqrtf(var + 1e-5f);
    #pragma unroll
    for (int k = 0; k < 3; k++) {
        int c = tid + k * 128;
        float yv = (v[k] - mean) * inv * g[c] + b[c];
        ys[c] = yv;
        out[(size_t)i * CS + c] = yv;
    }
    __syncthreads();

    if (tid < 32) {
        #pragma unroll
        for (int o = 0; o < 6; o++) {
            float sum = 0.f;
            for (int c = tid; c < CS; c += 32)
                sum = fmaf(ys[c], wsm[c * 6 + o], sum);
            #pragma unroll
            for (int off = 16; off > 0; off >>= 1)
                sum += __shfl_xor_sync(0xffffffffu, sum, off);
            if (tid == 0) u[o] = sum + bb_b[o];
        }
        if (tid == 0) {
            float bx = u[0], by = u[1], bz = u[2];
            float qinv = rsqrtf(1.f + bx*bx + by*by + bz*bz);
            float qw = qinv, x = bx * qinv, y = by * qinv, z = bz * qinv;
            float Ru[9] = {
                1 - 2*(y*y + z*z), 2*(x*y - qw*z),    2*(x*z + qw*y),
                2*(x*y + qw*z),    1 - 2*(x*x + z*z), 2*(y*z - qw*x),
                2*(x*z - qw*y),    2*(y*z + qw*x),    1 - 2*(x*x + y*y)};
            const float* R = rot + i * 9;
            float* ro = out + NN * CS + i * 9;
            #pragma unroll
            for (int r = 0; r < 3; r++)
                #pragma unroll
                for (int c = 0; c < 3; c++)
                    ro[r*3+c] = R[r*3+0]*Ru[0*3+c] + R[r*3+1]*Ru[1*3+c]
                              + R[r*3+2]*Ru[2*3+c];
            float tx = u[3], ty = u[4], tz = u[5];
            float* to = out + NN * CS + NN * 9 + i * 3;
            #pragma unroll
            for (int r = 0; r < 3; r++)
                to[r] = R[r*3+0]*tx + R[r*3+1]*ty + R[r*3+2]*tz + trans[i*3+r];
        }
    }
}

// ---------------------------------------------------------------------------
static cudaStream_t g_s1 = nullptr;
static cudaEvent_t  g_ev0, g_ev1, g_ev2, g_ev3;

extern "C" void kernel_launch(void* const* d_in, const int* in_sizes, int n_in,
                              void* d_out, int out_size)
{
    if (!g_s1) {
        cudaStreamCreateWithFlags(&g_s1, cudaStreamNonBlocking);
        cudaEventCreateWithFlags(&g_ev0, cudaEventDisableTiming);
        cudaEventCreateWithFlags(&g_ev1, cudaEventDisableTiming);
        cudaEventCreateWithFlags(&g_ev2, cudaEventDisableTiming);
        cudaEventCreateWithFlags(&g_ev3, cudaEventDisableTiming);
        cudaFuncSetAttribute(opair_tc_kernel,
                             cudaFuncAttributeMaxDynamicSharedMemorySize,
                             OPAIR_SMEM);
        cudaFuncSetAttribute(bias_tc_kernel,
                             cudaFuncAttributeMaxDynamicSharedMemorySize,
                             BIAS_SMEM);
    }

    const float* s      = (const float*)d_in[0];
    const float* p      = (const float*)d_in[1];
    const float* rot    = (const float*)d_in[2];
    const float* trans  = (const float*)d_in[3];
    const float* mask   = (const float*)d_in[4];
    const float* w_q    = (const float*)d_in[5];
    const float* b_q    = (const float*)d_in[6];
    const float* w_kv   = (const float*)d_in[7];
    const float* b_kv   = (const float*)d_in[8];
    const float* w_qp   = (const float*)d_in[9];
    const float* b_qp   = (const float*)d_in[10];
    const float* w_kvp  = (const float*)d_in[11];
    const float* b_kvp  = (const float*)d_in[12];
    const float* w_b    = (const float*)d_in[13];
    const float* b_b    = (const float*)d_in[14];
    const float* head_w = (const float*)d_in[15];
    const float* w_o    = (const float*)d_in[16];
    const float* b_o    = (const float*)d_in[17];
    const float* ln1_g  = (const float*)d_in[18];
    const float* ln1_b  = (const float*)d_in[19];
    const float* tw1    = (const float*)d_in[20];
    const float* tb1    = (const float*)d_in[21];
    const float* tw2    = (const float*)d_in[22];
    const float* tb2    = (const float*)d_in[23];
    const float* tw3    = (const float*)d_in[24];
    const float* tb3    = (const float*)d_in[25];
    const float* ln2_g  = (const float*)d_in[26];
    const float* ln2_b  = (const float*)d_in[27];
    const float* bb_w   = (const float*)d_in[28];
    const float* bb_b   = (const float*)d_in[29];
    float* out = (float*)d_out;

    float *wcat, *bcat, *proj, *ppart, *kpk, *kppk, *vpk, *a_, *cat_,
          *part, *partB, *x2;
    cudaGetSymbolAddress((void**)&wcat, g_wcat);
    cudaGetSymbolAddress((void**)&bcat, g_bcat);
    cudaGetSymbolAddress((void**)&proj, g_proj);
    cudaGetSymbolAddress((void**)&ppart, g_ppart);
    cudaGetSymbolAddress((void**)&kpk,  g_kpack);
    cudaGetSymbolAddress((void**)&kppk, g_kppack);
    cudaGetSymbolAddress((void**)&vpk,  g_vpack);
    cudaGetSymbolAddress((void**)&a_,   g_att);
    cudaGetSymbolAddress((void**)&cat_, g_cat);
    cudaGetSymbolAddress((void**)&part, g_part);
    cudaGetSymbolAddress((void**)&partB, g_partB);
    cudaGetSymbolAddress((void**)&x2,   g_x2);

    const long long SPC = (long long)NN * CS;

    // ---- fork: bias planes (tensor-core) on side stream --------------------
    cudaEventRecord(g_ev0, 0);
    cudaStreamWaitEvent(g_s1, g_ev0, 0);
    bias_tc_kernel<<<NN * NN / 64, 128, BIAS_SMEM, g_s1>>>(p, w_b, b_b, a_);
    cudaEventRecord(g_ev1, g_s1);

    // ---- main: projections (split-K 2), fused reduce+rotate+pack ----------
    pack_w_kernel<<<(CS * LDP / 4 + LDP / 4 + 255) / 256, 256>>>(
        w_q, b_q, w_kv, b_kv, w_qp, b_qp, w_kvp, b_kvp, wcat, bcat);
    gemm64_kernel<<<dim3(LDP / 64, 8, 2), 128>>>(
        s, CS, 0, 192,
        wcat, LDP, 0, (long long)192 * LDP,
        nullptr,
        ppart, LDP, 0, (long long)NN * LDP,
        192, 2, nullptr, 0, 0, 0);
    {
        const int TOT = NN*48 + HDS*NN*4*3 + HDS*NN*8 + NN*48;
        rotpack_kernel<<<(TOT + 255) / 256, 256>>>(ppart, bcat, rot, trans,
                                                   proj, kpk, kppk, vpk);
    }

    // join bias, then fused logits+softmax
    cudaStreamWaitEvent(0, g_ev1, 0);
    logits_softmax_kernel<<<dim3(64, HDS), 256>>>(proj, kpk, kppk, mask,
                                                  head_w, a_);

    // ---- fork: opair + w_o-high-K on side stream ---------------------------
    cudaEventRecord(g_ev2, 0);
    cudaStreamWaitEvent(g_s1, g_ev2, 0);
    opair_tc_kernel<<<NN, 128, OPAIR_SMEM, g_s1>>>(a_, p, cat_);
    gemm64_kernel<<<dim3(6, 8, 2), 128, 0, g_s1>>>(
        cat_ + 576, 2112, 0, 768,
        w_o + 576 * CS, CS, 0, (long long)768 * CS,
        nullptr,
        part + SPC, CS, 0, SPC,
        768, 2, nullptr, 0, 0, 0);
    cudaEventRecord(g_ev3, g_s1);

    // main: fused ov GEMM + postproc, then w_o low-K
    ovgemm_kernel<<<dim3(1, 8, HDS), 128>>>(a_, vpk, rot, trans, cat_);
    gemm64_kernel<<<dim3(6, 8, 1), 128>>>(
        cat_, 2112, 0, 0,
        w_o, CS, 0, 0,
        nullptr,
        part, CS, 0, 0,
        576, 1, nullptr, 0, 0, 0);
    cudaStreamWaitEvent(0, g_ev3, 0);

    // ---- reduce + residual + LN1 -------------------------------------------
    reduce_ln_kernel<<<NN, 128>>>(part, b_o, s, ln1_g, ln1_b, x2);

    // ---- transition MLP: reduces fused into next GEMM's A-staging ----------
    gemm64_kernel<<<dim3(6, 8, 3), 128>>>(
        x2, CS, 0, 128,
        tw1, CS, 0, (long long)128 * CS,
        nullptr,
        partB, CS, 0, SPC,
        128, 3, nullptr, 0, 0, 0);
    gemm64_kernel<<<dim3(6, 8, 3), 128>>>(
        partB, CS, 0, 128,
        tw2, CS, 0, (long long)128 * CS,
        nullptr,
        part, CS, 0, SPC,
        128, 3, tb1, SPC, 128, 1);
    gemm64_kernel<<<dim3(6, 8, 3), 128>>>(
        part, CS, 0, 128,
        tw3, CS, 0, (long long)128 * CS,
        nullptr,
        partB, CS, 0, SPC,
        128, 3, tb2, SPC, 128, 1);

    // ---- reduce + residual + LN2 + backbone update --------------------------
    lnbb_kernel<<<NN, 128>>>(partB, tb3, x2, ln2_g, ln2_b,
                             bb_w, bb_b, rot, trans, out);
}

// round 13
// speedup vs baseline: 1.0586x; 1.0586x over previous
#include <cuda_runtime.h>
#include <math.h>

// ---------------------------------------------------------------------------
// StructureLayer (IPA) — B=1, N=512, H=12, C_S=384, C_P=128, C_H=16,
// P_QK=4, P_V=8.  Output: [ s2 (512*384) | rot_new (512*9) | trans_new (512*3) ]
// ---------------------------------------------------------------------------

#define NN 512
#define CS 384
#define CP 128
#define HDS 12

// proj row layout: [ q(192) | kv(384) | qp(144) | kvp(432) ]  = 1152
#define LDP 1152
#define OFF_Q   0
#define OFF_KV  192
#define OFF_QP  576
#define OFF_KVP 720

#define SQK 0.14433756729740643f    // sqrt(1/48)
#define SB  0.5773502691896258f     // sqrt(1/3)
#define SHW 0.13608276348795434f    // sqrt(1/54)

// opair_tc dynamic smem: As 512*17 u32 + Bs 64*132 u32
#define OPAIR_SMEM ((512 * 17 + 64 * 132) * 4)

// ---- scratch (device globals) ----------------------------------------------
__device__ float g_wcat[CS * LDP];
__device__ float g_bcat[LDP];
__device__ float g_proj[NN * LDP];       // only q / qp sections used
__device__ float g_ppart[2 * NN * LDP];  // proj split-K partials
__device__ float g_kpack[HDS * NN * 16];
__device__ float g_kppack[HDS * NN * 12];
__device__ float g_vpack[HDS * NN * 64]; // [h][j][ v(16) | vp(24) | pad=0 ]
__device__ float g_att[HDS * NN * NN];   // bias planes, then probs [h][i][j]
__device__ float g_cat[NN * 2112];
__device__ float g_part[3 * NN * CS];    // split-K partials (A)
__device__ float g_partB[3 * NN * CS];   // split-K partials (B)
__device__ float g_x2[NN * CS];

// ---------------------------------------------------------------------------
// tf32 helpers
// ---------------------------------------------------------------------------
__device__ __forceinline__ unsigned cvt_tf32(float x)
{
    unsigned r;
    asm("cvt.rna.tf32.f32 %0, %1;" : "=r"(r) : "f"(x));
    return r;
}

__device__ __forceinline__ void mma_tf32(float* d, const unsigned* a,
                                         const unsigned* b)
{
    asm volatile(
        "mma.sync.aligned.m16n8k8.row.col.f32.tf32.tf32.f32 "
        "{%0,%1,%2,%3}, {%4,%5,%6,%7}, {%8,%9}, {%0,%1,%2,%3};\n"
        : "+f"(d[0]), "+f"(d[1]), "+f"(d[2]), "+f"(d[3])
        : "r"(a[0]), "r"(a[1]), "r"(a[2]), "r"(a[3]),
          "r"(b[0]), "r"(b[1]));
}

// A-load: optionally reduce 3 split-K partials + bias + relu on the fly.
__device__ __forceinline__ float4 ldA4(const float* p,
                                       const float* abias, int bcol,
                                       long long SP, int arelu)
{
    float4 v = *(const float4*)p;
    if (abias) {
        float4 v1 = *(const float4*)(p + SP);
        float4 v2 = *(const float4*)(p + 2 * SP);
        float4 bb = *(const float4*)(abias + bcol);
        v.x += v1.x + v2.x + bb.x;
        v.y += v1.y + v2.y + bb.y;
        v.z += v1.z + v2.z + bb.z;
        v.w += v1.w + v2.w + bb.w;
        if (arelu) {
            v.x = fmaxf(v.x, 0.f); v.y = fmaxf(v.y, 0.f);
            v.z = fmaxf(v.z, 0.f); v.w = fmaxf(v.w, 0.f);
        }
    }
    return v;
}

// ---------------------------------------------------------------------------
// Pack projection weights/biases into one (384 x 1152) matrix. float4 copies.
// ---------------------------------------------------------------------------
__global__ void pack_w_kernel(const float* __restrict__ w_q,  const float* __restrict__ b_q,
                              const float* __restrict__ w_kv, const float* __restrict__ b_kv,
                              const float* __restrict__ w_qp, const float* __restrict__ b_qp,
                              const float* __restrict__ w_kvp,const float* __restrict__ b_kvp,
                              float* __restrict__ wcat, float* __restrict__ bcat)
{
    const int NW4 = CS * LDP / 4;
    int idx = blockIdx.x * blockDim.x + threadIdx.x;
    if (idx < NW4) {
        int r = idx / (LDP / 4), c = (idx % (LDP / 4)) * 4;
        float4 v;
        if      (c < 192) v = *(const float4*)(w_q  + r * 192 + c);
        else if (c < 576) v = *(const float4*)(w_kv + r * 384 + (c - 192));
        else if (c < 720) v = *(const float4*)(w_qp + r * 144 + (c - 576));
        else              v = *(const float4*)(w_kvp + r * 432 + (c - 720));
        *(float4*)(wcat + r * LDP + c) = v;
    } else if (idx < NW4 + LDP / 4) {
        int c = (idx - NW4) * 4;
        float4 v;
        if      (c < 192) v = *(const float4*)(b_q  + c);
        else if (c < 576) v = *(const float4*)(b_kv + (c - 192));
        else if (c < 720) v = *(const float4*)(b_qp + (c - 576));
        else              v = *(const float4*)(b_kvp + (c - 720));
        *(float4*)(bcat + c) = v;
    }
}

// ---------------------------------------------------------------------------
// tf32 tensor-core GEMM: 64x64 tile, 128 threads, double-buffered smem.
// z = zb*KS + zk (batch x split-K).  Optional fused A-side 3-partial
// reduce + bias + relu (abias != nullptr).
// ---------------------------------------------------------------------------
__global__ void __launch_bounds__(128)
gemm64_kernel(const float* __restrict__ A, int lda, long long sAz, long long sAk,
              const float* __restrict__ B, int ldb, long long sBz, long long sBk,
              const float* __restrict__ bias,
              float* __restrict__ C, int ldc, long long sCz, long long sCk,
              int K, int KS,
              const float* __restrict__ abias, long long aSP, int aKoff, int arelu)
{
    const int zb = blockIdx.z / KS, zk = blockIdx.z % KS;
    A += (size_t)zb * (size_t)sAz + (size_t)zk * (size_t)sAk;
    B += (size_t)zb * (size_t)sBz + (size_t)zk * (size_t)sBk;
    C += (size_t)zb * (size_t)sCz + (size_t)zk * (size_t)sCk;
    const int azoff = zk * aKoff;

    __shared__ __align__(16) unsigned As[2][16][72];
    __shared__ __align__(16) unsigned Bs[2][16][72];

    const int bm = blockIdx.y * 64, bn = blockIdx.x * 64;
    const int tid = threadIdx.x;
    const int lane = tid & 31, warp = tid >> 5;
    const int g = lane >> 2, t4 = lane & 3;
    const int wm = (warp >> 1) * 32, wn = (warp & 1) * 32;

    const int ar = tid >> 2, ak = (tid & 3) * 4;
    const int br = tid >> 4, bc = (tid & 15) * 4;

    const float* Ab = A + (size_t)bm * lda;

    float4 ra0, ra1, rb0, rb1;
    ra0 = ldA4(Ab + (size_t)ar * lda + ak, abias, azoff + ak, aSP, arelu);
    ra1 = ldA4(Ab + (size_t)(ar + 32) * lda + ak, abias, azoff + ak, aSP, arelu);
    rb0 = *(const float4*)(B + (size_t)br * ldb + bn + bc);
    rb1 = *(const float4*)(B + (size_t)(br + 8) * ldb + bn + bc);

    As[0][ak+0][ar] = cvt_tf32(ra0.x); As[0][ak+1][ar] = cvt_tf32(ra0.y);
    As[0][ak+2][ar] = cvt_tf32(ra0.z); As[0][ak+3][ar] = cvt_tf32(ra0.w);
    As[0][ak+0][ar+32] = cvt_tf32(ra1.x); As[0][ak+1][ar+32] = cvt_tf32(ra1.y);
    As[0][ak+2][ar+32] = cvt_tf32(ra1.z); As[0][ak+3][ar+32] = cvt_tf32(ra1.w);
    {
        uint4 u0 = make_uint4(cvt_tf32(rb0.x), cvt_tf32(rb0.y),
                              cvt_tf32(rb0.z), cvt_tf32(rb0.w));
        uint4 u1 = make_uint4(cvt_tf32(rb1.x), cvt_tf32(rb1.y),
                              cvt_tf32(rb1.z), cvt_tf32(rb1.w));
        *(uint4*)&Bs[0][br][bc]     = u0;
        *(uint4*)&Bs[0][br + 8][bc] = u1;
    }
    __syncthreads();

    float acc[2][4][4];
    #pragma unroll
    for (int mt = 0; mt < 2; mt++)
        #pragma unroll
        for (int nt = 0; nt < 4; nt++)
            #pragma unroll
            for (int r = 0; r < 4; r++) acc[mt][nt][r] = 0.f;

    int buf = 0;
    for (int k0 = 0; k0 < K; k0 += 16) {
        const bool more = (k0 + 16) < K;
        if (more) {
            int kc = k0 + 16 + ak;
            ra0 = ldA4(Ab + (size_t)ar * lda + kc, abias, azoff + kc, aSP, arelu);
            ra1 = ldA4(Ab + (size_t)(ar + 32) * lda + kc, abias, azoff + kc, aSP, arelu);
            rb0 = *(const float4*)(B + (size_t)(k0 + 16 + br) * ldb + bn + bc);
            rb1 = *(const float4*)(B + (size_t)(k0 + 16 + br + 8) * ldb + bn + bc);
        }
        #pragma unroll
        for (int kk = 0; kk < 16; kk += 8) {
            unsigned af[2][4], bf[4][2];
            #pragma unroll
            for (int mt = 0; mt < 2; mt++) {
                int m0 = wm + mt * 16 + g;
                af[mt][0] = As[buf][kk + t4][m0];
                af[mt][1] = As[buf][kk + t4][m0 + 8];
                af[mt][2] = As[buf][kk + 4 + t4][m0];
                af[mt][3] = As[buf][kk + 4 + t4][m0 + 8];
            }
            #pragma unroll
            for (int nt = 0; nt < 4; nt++) {
                int n0 = wn + nt * 8 + g;
                bf[nt][0] = Bs[buf][kk + t4][n0];
                bf[nt][1] = Bs[buf][kk + 4 + t4][n0];
            }
            #pragma unroll
            for (int mt = 0; mt < 2; mt++)
                #pragma unroll
                for (int nt = 0; nt < 4; nt++)
                    mma_tf32(acc[mt][nt], af[mt], bf[nt]);
        }
        if (more) {
            buf ^= 1;
            __syncthreads();
            As[buf][ak+0][ar] = cvt_tf32(ra0.x); As[buf][ak+1][ar] = cvt_tf32(ra0.y);
            As[buf][ak+2][ar] = cvt_tf32(ra0.z); As[buf][ak+3][ar] = cvt_tf32(ra0.w);
            As[buf][ak+0][ar+32] = cvt_tf32(ra1.x); As[buf][ak+1][ar+32] = cvt_tf32(ra1.y);
            As[buf][ak+2][ar+32] = cvt_tf32(ra1.z); As[buf][ak+3][ar+32] = cvt_tf32(ra1.w);
            uint4 u0 = make_uint4(cvt_tf32(rb0.x), cvt_tf32(rb0.y),
                                  cvt_tf32(rb0.z), cvt_tf32(rb0.w));
            uint4 u1 = make_uint4(cvt_tf32(rb1.x), cvt_tf32(rb1.y),
                                  cvt_tf32(rb1.z), cvt_tf32(rb1.w));
            *(uint4*)&Bs[buf][br][bc]     = u0;
            *(uint4*)&Bs[buf][br + 8][bc] = u1;
            __syncthreads();
        }
    }

    #pragma unroll
    for (int mt = 0; mt < 2; mt++) {
        int row0 = bm + wm + mt * 16 + g;
        #pragma unroll
        for (int nt = 0; nt < 4; nt++) {
            int col = bn + wn + nt * 8 + t4 * 2;
            float b0 = 0.f, b1 = 0.f;
            if (bias) { b0 = bias[col]; b1 = bias[col + 1]; }
            float2 v0 = make_float2(acc[mt][nt][0] + b0, acc[mt][nt][1] + b1);
            float2 v1 = make_float2(acc[mt][nt][2] + b0, acc[mt][nt][3] + b1);
            *(float2*)(C + (size_t)row0 * ldc + col)       = v0;
            *(float2*)(C + (size_t)(row0 + 8) * ldc + col) = v1;
        }
    }
}

// ---------------------------------------------------------------------------
// bias planes: att[h][i][j] = (p[i,j,:]·w_b[:,h] + b_b[h]) * sqrt(1/3)
// ibase: starting residue row (for i-split pipelining).
// ---------------------------------------------------------------------------
__global__ void bias_kernel(const float* __restrict__ p,
                            const float* __restrict__ w_b,
                            const float* __restrict__ b_b,
                            float* __restrict__ att, int ibase)
{
    __shared__ float wbt[HDS][CP];
    __shared__ float bbs[HDS];
    const int tid = threadIdx.x;
    #pragma unroll
    for (int k = 0; k < 6; k++) {
        int e = tid + k * 256;
        int h = e / CP, c = e % CP;
        wbt[h][c] = w_b[c * HDS + h];
    }
    if (tid < HDS) bbs[tid] = b_b[tid];
    __syncthreads();

    const int gw = blockIdx.x * 8 + (tid >> 5);
    const int lane = tid & 31;
    const int i = ibase + (gw >> 4);
    const int j = ((gw & 15) << 5) + lane;

    float acc[HDS];
    #pragma unroll
    for (int h = 0; h < HDS; h++) acc[h] = 0.f;

    const float4* prow = (const float4*)(p + ((size_t)i * NN + j) * CP);
    #pragma unroll 4
    for (int c4 = 0; c4 < 32; c4++) {
        float4 pv = prow[c4];
        #pragma unroll
        for (int h = 0; h < HDS; h++) {
            float4 wv = ((const float4*)&wbt[h][0])[c4];
            acc[h] = fmaf(pv.x, wv.x,
                     fmaf(pv.y, wv.y,
                     fmaf(pv.z, wv.z,
                     fmaf(pv.w, wv.w, acc[h]))));
        }
    }
    #pragma unroll
    for (int h = 0; h < HDS; h++)
        att[((size_t)(h * NN) + i) * NN + j] = (acc[h] + bbs[h]) * SB;
}

// ---------------------------------------------------------------------------
// ov GEMM (att @ [v|vp], per-head) with fused postproc epilogue:
// writes o / rotated-op / norms directly into cat.  grid (1, 8, HDS).
// ---------------------------------------------------------------------------
__global__ void __launch_bounds__(128)
ovgemm_kernel(const float* __restrict__ att,
              const float* __restrict__ vpk,
              const float* __restrict__ rot,
              const float* __restrict__ trans,
              float* __restrict__ cat)
{
    const int h = blockIdx.z;
    const float* A = att + (size_t)h * NN * NN;
    const float* B = vpk + (size_t)h * NN * 64;

    __shared__ __align__(16) unsigned As[2][16][72];
    __shared__ __align__(16) unsigned Bs[2][16][72];
    __shared__ float sm[64][41];

    const int bm = blockIdx.y * 64;
    const int tid = threadIdx.x;
    const int lane = tid & 31, warp = tid >> 5;
    const int g = lane >> 2, t4 = lane & 3;
    const int wm = (warp >> 1) * 32, wn = (warp & 1) * 32;

    const int ar = tid >> 2, ak = (tid & 3) * 4;
    const int br = tid >> 4, bc = (tid & 15) * 4;

    const float* Ab = A + (size_t)bm * NN;

    float4 ra0, ra1, rb0, rb1;
    ra0 = *(const float4*)(Ab + (size_t)ar * NN + ak);
    ra1 = *(const float4*)(Ab + (size_t)(ar + 32) * NN + ak);
    rb0 = *(const float4*)(B + (size_t)br * 64 + bc);
    rb1 = *(const float4*)(B + (size_t)(br + 8) * 64 + bc);

    As[0][ak+0][ar] = cvt_tf32(ra0.x); As[0][ak+1][ar] = cvt_tf32(ra0.y);
    As[0][ak+2][ar] = cvt_tf32(ra0.z); As[0][ak+3][ar] = cvt_tf32(ra0.w);
    As[0][ak+0][ar+32] = cvt_tf32(ra1.x); As[0][ak+1][ar+32] = cvt_tf32(ra1.y);
    As[0][ak+2][ar+32] = cvt_tf32(ra1.z); As[0][ak+3][ar+32] = cvt_tf32(ra1.w);
    {
        uint4 u0 = make_uint4(cvt_tf32(rb0.x), cvt_tf32(rb0.y),
                              cvt_tf32(rb0.z), cvt_tf32(rb0.w));
        uint4 u1 = make_uint4(cvt_tf32(rb1.x), cvt_tf32(rb1.y),
                              cvt_tf32(rb1.z), cvt_tf32(rb1.w));
        *(uint4*)&Bs[0][br][bc]     = u0;
        *(uint4*)&Bs[0][br + 8][bc] = u1;
    }
    __syncthreads();

    float acc[2][4][4];
    #pragma unroll
    for (int mt = 0; mt < 2; mt++)
        #pragma unroll
        for (int nt = 0; nt < 4; nt++)
            #pragma unroll
            for (int r = 0; r < 4; r++) acc[mt][nt][r] = 0.f;

    int buf = 0;
    for (int k0 = 0; k0 < NN; k0 += 16) {
        const bool more = (k0 + 16) < NN;
        if (more) {
            ra0 = *(const float4*)(Ab + (size_t)ar * NN + k0 + 16 + ak);
            ra1 = *(const float4*)(Ab + (size_t)(ar + 32) * NN + k0 + 16 + ak);
            rb0 = *(const float4*)(B + (size_t)(k0 + 16 + br) * 64 + bc);
            rb1 = *(const float4*)(B + (size_t)(k0 + 16 + br + 8) * 64 + bc);
        }
        #pragma unroll
        for (int kk = 0; kk < 16; kk += 8) {
            unsigned af[2][4], bf[4][2];
            #pragma unroll
            for (int mt = 0; mt < 2; mt++) {
                int m0 = wm + mt * 16 + g;
                af[mt][0] = As[buf][kk + t4][m0];
                af[mt][1] = As[buf][kk + t4][m0 + 8];
                af[mt][2] = As[buf][kk + 4 + t4][m0];
                af[mt][3] = As[buf][kk + 4 + t4][m0 + 8];
            }
            #pragma unroll
            for (int nt = 0; nt < 4; nt++) {
                int n0 = wn + nt * 8 + g;
                bf[nt][0] = Bs[buf][kk + t4][n0];
                bf[nt][1] = Bs[buf][kk + 4 + t4][n0];
            }
            #pragma unroll
            for (int mt = 0; mt < 2; mt++)
                #pragma unroll
                for (int nt = 0; nt < 4; nt++)
                    mma_tf32(acc[mt][nt], af[mt], bf[nt]);
        }
        if (more) {
            buf ^= 1;
            __syncthreads();
            As[buf][ak+0][ar] = cvt_tf32(ra0.x); As[buf][ak+1][ar] = cvt_tf32(ra0.y);
            As[buf][ak+2][ar] = cvt_tf32(ra0.z); As[buf][ak+3][ar] = cvt_tf32(ra0.w);
            As[buf][ak+0][ar+32] = cvt_tf32(ra1.x); As[buf][ak+1][ar+32] = cvt_tf32(ra1.y);
            As[buf][ak+2][ar+32] = cvt_tf32(ra1.z); As[buf][ak+3][ar+32] = cvt_tf32(ra1.w);
            uint4 u0 = make_uint4(cvt_tf32(rb0.x), cvt_tf32(rb0.y),
                                  cvt_tf32(rb0.z), cvt_tf32(rb0.w));
            uint4 u1 = make_uint4(cvt_tf32(rb1.x), cvt_tf32(rb1.y),
                                  cvt_tf32(rb1.z), cvt_tf32(rb1.w));
            *(uint4*)&Bs[buf][br][bc]     = u0;
            *(uint4*)&Bs[buf][br + 8][bc] = u1;
            __syncthreads();
        }
    }

    #pragma unroll
    for (int mt = 0; mt < 2; mt++) {
        int r0 = wm + mt * 16 + g;
        #pragma unroll
        for (int nt = 0; nt < 4; nt++) {
            int col = wn + nt * 8 + t4 * 2;
            if (col < 40) {
                sm[r0][col]       = acc[mt][nt][0];
                sm[r0][col + 1]   = acc[mt][nt][1];
                sm[r0 + 8][col]     = acc[mt][nt][2];
                sm[r0 + 8][col + 1] = acc[mt][nt][3];
            }
        }
    }
    __syncthreads();

    #pragma unroll
    for (int l = 0; l < 8; l++) {
        int e = tid + l * 128;
        int r = e >> 4, c = e & 15;
        cat[(size_t)(bm + r) * 2112 + h * 16 + c] = sm[r][c];
    }
    #pragma unroll
    for (int l = 0; l < 4; l++) {
        int e = tid + l * 128;
        int r = e >> 3, pp = e & 7;
        int i = bm + r;
        float vx = sm[r][16 + pp*3 + 0] - trans[i*3 + 0];
        float vy = sm[r][16 + pp*3 + 1] - trans[i*3 + 1];
        float vz = sm[r][16 + pp*3 + 2] - trans[i*3 + 2];
        const float* R = rot + i * 9;
        float ox = R[0]*vx + R[3]*vy + R[6]*vz;
        float oy = R[1]*vx + R[4]*vy + R[7]*vz;
        float oz = R[2]*vx + R[5]*vy + R[8]*vz;
        float* ci = cat + (size_t)i * 2112;
        ci[192 + h*24 + pp*3 + 0] = ox;
        ci[192 + h*24 + pp*3 + 1] = oy;
        ci[192 + h*24 + pp*3 + 2] = oz;
        ci[480 + h*8 + pp] = sqrtf(ox*ox + oy*oy + oz*oz + 1e-8f);
    }
}

// ---------------------------------------------------------------------------
// o_pair via tensor cores: per-i block computes (16x512)@(512x128)
// ---------------------------------------------------------------------------
extern __shared__ unsigned opair_smem[];
__global__ void __launch_bounds__(128)
opair_tc_kernel(const float* __restrict__ att,
                const float* __restrict__ p,
                float* __restrict__ cat)
{
    const int i = blockIdx.x;
    unsigned* As = opair_smem;                 // [j][h] stride 17
    unsigned* Bs = opair_smem + 512 * 17;      // [jj][c] stride 132
    const int tid = threadIdx.x;

    for (int idx = tid; idx < HDS * NN; idx += 128) {
        int j = idx & 511, h = idx >> 9;
        As[j * 17 + h] = cvt_tf32(att[((size_t)(h * NN) + i) * NN + j]);
    }
    for (int idx = tid; idx < 4 * NN; idx += 128) {
        int j = idx & 511, h = 12 + (idx >> 9);
        As[j * 17 + h] = 0u;
    }

    const int lane = tid & 31, warp = tid >> 5;
    const int g = lane >> 2, t4 = lane & 3;
    const int wn = warp * 32;

    float acc[4][4];
    #pragma unroll
    for (int nt = 0; nt < 4; nt++)
        #pragma unroll
        for (int r = 0; r < 4; r++) acc[nt][r] = 0.f;

    const float4* pi4 = (const float4*)(p + (size_t)i * NN * CP);

    for (int j0 = 0; j0 < NN; j0 += 64) {
        __syncthreads();
        #pragma unroll
        for (int l = 0; l < 16; l++) {
            int e = tid + l * 128;
            int jj = e >> 5, c4 = e & 31;
            float4 v = pi4[(size_t)(j0 + jj) * 32 + c4];
            uint4 u = make_uint4(cvt_tf32(v.x), cvt_tf32(v.y),
                                 cvt_tf32(v.z), cvt_tf32(v.w));
            *(uint4*)&Bs[jj * 132 + c4 * 4] = u;
        }
        __syncthreads();
        #pragma unroll
        for (int ks = 0; ks < 8; ks++) {
            unsigned af[4];
            int kg = (j0 + ks * 8 + t4) * 17;
            int kg4 = (j0 + ks * 8 + 4 + t4) * 17;
            af[0] = As[kg + g];
            af[1] = As[kg + g + 8];
            af[2] = As[kg4 + g];
            af[3] = As[kg4 + g + 8];
            #pragma unroll
            for (int nt = 0; nt < 4; nt++) {
                unsigned bf[2];
                int n0 = wn + nt * 8 + g;
                bf[0] = Bs[(ks * 8 + t4) * 132 + n0];
                bf[1] = Bs[(ks * 8 + 4 + t4) * 132 + n0];
                mma_tf32(acc[nt], af, bf);
            }
        }
    }

    float* dst = cat + (size_t)i * 2112 + 576;
    #pragma unroll
    for (int nt = 0; nt < 4; nt++) {
        int col = wn + nt * 8 + t4 * 2;
        dst[g * 128 + col]     = acc[nt][0];
        dst[g * 128 + col + 1] = acc[nt][1];
        if (g + 8 < HDS) {
            dst[(g + 8) * 128 + col]     = acc[nt][2];
            dst[(g + 8) * 128 + col + 1] = acc[nt][3];
        }
    }
}

// ---------------------------------------------------------------------------
// Fused proj split-K reduce + bias + rotate + repack.
// ---------------------------------------------------------------------------
__global__ void rotpack_kernel(const float* __restrict__ ppart,
                               const float* __restrict__ bcat,
                               const float* __restrict__ rot,
                               const float* __restrict__ trans,
                               float* __restrict__ proj,
                               float* __restrict__ kpack,
                               float* __restrict__ kppack,
                               float* __restrict__ vpack)
{
    const long long SP = (long long)NN * LDP;
    const int S0 = NN * 48;
    const int S1 = S0 + HDS * NN * 4;
    const int S2 = S1 + HDS * NN * 4;
    const int S3 = S2 + HDS * NN * 4;
    const int S4 = S3 + HDS * NN * 8;
    const int S5 = S4 + NN * 48;
    int idx = blockIdx.x * blockDim.x + threadIdx.x;

    if (idx < S0) {
        int j = idx / 48, c = (idx % 48) * 4;
        const float* p0 = ppart + (size_t)j * LDP + c;
        float4 a = *(const float4*)p0;
        float4 b = *(const float4*)(p0 + SP);
        float4 bb = *(const float4*)(bcat + c);
        *(float4*)(proj + (size_t)j * LDP + c) =
            make_float4(a.x+b.x+bb.x, a.y+b.y+bb.y, a.z+b.z+bb.z, a.w+b.w+bb.w);
    } else if (idx < S1) {
        int t = idx - S0;
        int c = (t & 3) * 4, j = (t >> 2) & 511, h = t >> 11;
        int col = OFF_KV + h * 32 + c;
        const float* p0 = ppart + (size_t)j * LDP + col;
        float4 a = *(const float4*)p0;
        float4 b = *(const float4*)(p0 + SP);
        float4 bb = *(const float4*)(bcat + col);
        *(float4*)(kpack + (((size_t)h * NN) + j) * 16 + c) =
            make_float4(a.x+b.x+bb.x, a.y+b.y+bb.y, a.z+b.z+bb.z, a.w+b.w+bb.w);
    } else if (idx < S2) {
        int t = idx - S1;
        int c = (t & 3) * 4, j = (t >> 2) & 511, h = t >> 11;
        int col = OFF_KV + h * 32 + 16 + c;
        const float* p0 = ppart + (size_t)j * LDP + col;
        float4 a = *(const float4*)p0;
        float4 b = *(const float4*)(p0 + SP);
        float4 bb = *(const float4*)(bcat + col);
        *(float4*)(vpack + (((size_t)h * NN) + j) * 64 + c) =
            make_float4(a.x+b.x+bb.x, a.y+b.y+bb.y, a.z+b.z+bb.z, a.w+b.w+bb.w);
    } else if (idx < S4) {
        int t = idx - S2;
        int pp, j, h;
        float* dst;
        if (t < HDS * NN * 4) {
            pp = t & 3; j = (t >> 2) & 511; h = t >> 11;
            dst = kppack + (((size_t)h * NN) + j) * 12 + pp * 3;
        } else {
            t -= HDS * NN * 4;
            int vp = t & 7; j = (t >> 3) & 511; h = t >> 12;
            pp = 4 + vp;
            dst = vpack + (((size_t)h * NN) + j) * 64 + 16 + vp * 3;
        }
        int col = OFF_KVP + h * 36 + pp * 3;
        const float* p0 = ppart + (size_t)j * LDP + col;
        float x = p0[0] + p0[SP + 0] + bcat[col + 0];
        float y = p0[1] + p0[SP + 1] + bcat[col + 1];
        float z = p0[2] + p0[SP + 2] + bcat[col + 2];
        const float* R = rot + j * 9;
        const float* tr = trans + j * 3;
        dst[0] = R[0]*x + R[1]*y + R[2]*z + tr[0];
        dst[1] = R[3]*x + R[4]*y + R[5]*z + tr[1];
        dst[2] = R[6]*x + R[7]*y + R[8]*z + tr[2];
    } else if (idx < S5) {
        int t = idx - S4;
        int pt = t % 48, j = t / 48;
        int col = OFF_QP + pt * 3;
        const float* p0 = ppart + (size_t)j * LDP + col;
        float x = p0[0] + p0[SP + 0] + bcat[col + 0];
        float y = p0[1] + p0[SP + 1] + bcat[col + 1];
        float z = p0[2] + p0[SP + 2] + bcat[col + 2];
        const float* R = rot + j * 9;
        const float* tr = trans + j * 3;
        float* pv = proj + (size_t)j * LDP + col;
        pv[0] = R[0]*x + R[1]*y + R[2]*z + tr[0];
        pv[1] = R[3]*x + R[4]*y + R[5]*z + tr[1];
        pv[2] = R[6]*x + R[7]*y + R[8]*z + tr[2];
    }
}

// ---------------------------------------------------------------------------
// Fused logits + softmax.  Block = (i-tile of 8, head h).  256 threads.
// ibase: starting residue (for i-split pipelining).
// ---------------------------------------------------------------------------
__global__ void logits_softmax_kernel(const float* __restrict__ proj,
                                      const float* __restrict__ kpack,
                                      const float* __restrict__ kppack,
                                      const float* __restrict__ mask,
                                      const float* __restrict__ head_w,
                                      float* __restrict__ att, int ibase)
{
    const int i0 = ibase + blockIdx.x * 8, h = blockIdx.y;
    const int tid = threadIdx.x;

    __shared__ float att_s[8][NN];
    __shared__ float kt[64][17];
    __shared__ float kpt[64][13];
    __shared__ float q_s[8][17];
    __shared__ float qp_s[8][13];
    __shared__ float m_i[8];
    __shared__ float sh_hw;

    if (tid < 128) {
        int il = tid >> 4, c = tid & 15;
        q_s[il][c] = proj[(size_t)(i0 + il) * LDP + OFF_Q + h * 16 + c];
    } else if (tid < 224) {
        int e = tid - 128;
        int il = e / 12, c = e % 12;
        qp_s[il][c] = proj[(size_t)(i0 + il) * LDP + OFF_QP + h * 12 + c];
    } else if (tid < 232) {
        m_i[tid - 224] = mask[i0 + (tid - 224)];
    } else if (tid == 232) {
        float w = head_w[h];
        float sp = fmaxf(w, 0.f) + log1pf(expf(-fabsf(w)));
        sh_hw = sp * SHW;
    }

    const float* kb  = kpack  + (size_t)(h * NN) * 16;
    const float* kpb = kppack + (size_t)(h * NN) * 12;

    const int jl = tid & 63, ig = tid >> 6;

    for (int j0 = 0; j0 < NN; j0 += 64) {
        #pragma unroll
        for (int k = 0; k < 4; k++) {
            int e = tid + k * 256;
            int r = e >> 4, c = e & 15;
            kt[r][c] = kb[(size_t)(j0 + r) * 16 + c];
        }
        #pragma unroll
        for (int k = 0; k < 3; k++) {
            int e = tid + k * 256;
            if (e < 768) {
                int r = e / 12, c = e % 12;
                kpt[r][c] = kpb[(size_t)(j0 + r) * 12 + c];
            }
        }
        __syncthreads();

        float mj = mask[j0 + jl];
        float hw = sh_hw;
        #pragma unroll
        for (int ii = 0; ii < 2; ii++) {
            int il = ig * 2 + ii;
            float qk = 0.f;
            #pragma unroll
            for (int c = 0; c < 16; c++) qk = fmaf(q_s[il][c], kt[jl][c], qk);
            float d2 = 0.f;
            #pragma unroll
            for (int d = 0; d < 12; d++) {
                float dd = qp_s[il][d] - kpt[jl][d];
                d2 = fmaf(dd, dd, d2);
            }
            float bias = att[((size_t)(h * NN) + i0 + il) * NN + j0 + jl];
            att_s[il][j0 + jl] = qk * SQK + bias - 0.5f * hw * d2
                               + (m_i[il] * mj - 1.0f) * 100000.0f;
        }
        __syncthreads();
    }

    const int w = tid >> 5, lane = tid & 31;
    float vals[16];
    float vmax = -1e30f;
    #pragma unroll
    for (int k = 0; k < 16; k++) {
        vals[k] = att_s[w][lane + 32 * k];
        vmax = fmaxf(vmax, vals[k]);
    }
    #pragma unroll
    for (int o = 16; o > 0; o >>= 1)
        vmax = fmaxf(vmax, __shfl_xor_sync(0xffffffffu, vmax, o));
    float sum = 0.f;
    #pragma unroll
    for (int k = 0; k < 16; k++) { vals[k] = expf(vals[k] - vmax); sum += vals[k]; }
    #pragma unroll
    for (int o = 16; o > 0; o >>= 1)
        sum += __shfl_xor_sync(0xffffffffu, sum, o);
    float inv = 1.0f / sum;
    float* arow = att + ((size_t)(h * NN) + i0 + w) * NN;
    #pragma unroll
    for (int k = 0; k < 16; k++)
        arow[lane + 32 * k] = vals[k] * inv;
}

// ---------------------------------------------------------------------------
// 3-way split-K reduce + bias + residual + LayerNorm.  Block/row, 128 thr.
// ---------------------------------------------------------------------------
__global__ void reduce_ln_kernel(const float* __restrict__ part,
                                 const float* __restrict__ bias,
                                 const float* __restrict__ res,
                                 const float* __restrict__ g,
                                 const float* __restrict__ b,
                                 float* __restrict__ y)
{
    __shared__ float rs[128], rs2[128];
    const int i = blockIdx.x, tid = threadIdx.x;
    const size_t SP = (size_t)NN * CS;
    float v[3];
    float sm = 0.f, sm2 = 0.f;
    #pragma unroll
    for (int k = 0; k < 3; k++) {
        int c = tid + k * 128;
        size_t o = (size_t)i * CS + c;
        float x = part[o] + part[SP + o] + part[2*SP + o] + bias[c] + res[o];
        v[k] = x;
        sm += x; sm2 += x * x;
    }
    rs[tid] = sm; rs2[tid] = sm2;
    __syncthreads();
    for (int st = 64; st > 0; st >>= 1) {
        if (tid < st) { rs[tid] += rs[tid + st]; rs2[tid] += rs2[tid + st]; }
        __syncthreads();
    }
    float mean = rs[0] * (1.0f / CS);
    float var  = rs2[0] * (1.0f / CS) - mean * mean;
    float inv  = rsqrtf(var + 1e-5f);
    #pragma unroll
    for (int k = 0; k < 3; k++) {
        int c = tid + k * 128;
        y[(size_t)i * CS + c] = (v[k] - mean) * inv * g[c] + b[c];
    }
}

// ---------------------------------------------------------------------------
// Fused: 3-way reduce + bias + residual + LayerNorm2 + backbone projection
// + quaternion frame update.  Block per row, 128 threads.
// ---------------------------------------------------------------------------
__global__ void lnbb_kernel(const float* __restrict__ part,
                            const float* __restrict__ bias,
                            const float* __restrict__ res,
                            const float* __restrict__ g,
                            const float* __restrict__ b,
                            const float* __restrict__ bb_w,
                            const float* __restrict__ bb_b,
                            const float* __restrict__ rot,
                            const float* __restrict__ trans,
                            float* __restrict__ out)
{
    __shared__ float rs[128], rs2[128], ys[CS], wsm[CS * 6], u[6];
    const int i = blockIdx.x, tid = threadIdx.x;
    const size_t SP = (size_t)NN * CS;

    #pragma unroll
    for (int k = 0; k < 18; k++) wsm[tid + k * 128] = bb_w[tid + k * 128];

    float v[3];
    float sm = 0.f, sm2 = 0.f;
    #pragma unroll
    for (int k = 0; k < 3; k++) {
        int c = tid + k * 128;
        size_t o = (size_t)i * CS + c;
        float x = part[o] + part[SP + o] + part[2*SP + o] + bias[c] + res[o];
        v[k] = x;
        sm += x; sm2 += x * x;
    }
    rs[tid] = sm; rs2[tid] = sm2;
    __syncthreads();
    for (int st = 64; st > 0; st >>= 1) {
        if (tid < st) { rs[tid] += rs[tid + st]; rs2[tid] += rs2[tid + st]; }
        __syncthreads();
    }
    float mean = rs[0] * (1.0f / CS);
    float var  = rs2[0] * (1.0f / CS) - mean * mean;
    float inv  = rsqrtf(var + 1e-5f);
    #pragma unroll
    for (int k = 0; k < 3; k++) {
        int c = tid + k * 128;
        float yv = (v[k] - mean) * inv * g[c] + b[c];
        ys[c] = yv;
        out[(size_t)i * CS + c] = yv;
    }
    __syncthreads();

    if (tid < 32) {
        #pragma unroll
        for (int o = 0; o < 6; o++) {
            float sum = 0.f;
            for (int c = tid; c < CS; c += 32)
                sum = fmaf(ys[c], wsm[c * 6 + o], sum);
            #pragma unroll
            for (int off = 16; off > 0; off >>= 1)
                sum += __shfl_xor_sync(0xffffffffu, sum, off);
            if (tid == 0) u[o] = sum + bb_b[o];
        }
        if (tid == 0) {
            float bx = u[0], by = u[1], bz = u[2];
            float qinv = rsqrtf(1.f + bx*bx + by*by + bz*bz);
            float qw = qinv, x = bx * qinv, y = by * qinv, z = bz * qinv;
            float Ru[9] = {
                1 - 2*(y*y + z*z), 2*(x*y - qw*z),    2*(x*z + qw*y),
                2*(x*y + qw*z),    1 - 2*(x*x + z*z), 2*(y*z - qw*x),
                2*(x*z - qw*y),    2*(y*z + qw*x),    1 - 2*(x*x + y*y)};
            const float* R = rot + i * 9;
            float* ro = out + NN * CS + i * 9;
            #pragma unroll
            for (int r = 0; r < 3; r++)
                #pragma unroll
                for (int c = 0; c < 3; c++)
                    ro[r*3+c] = R[r*3+0]*Ru[0*3+c] + R[r*3+1]*Ru[1*3+c]
                              + R[r*3+2]*Ru[2*3+c];
            float tx = u[3], ty = u[4], tz = u[5];
            float* to = out + NN * CS + NN * 9 + i * 3;
            #pragma unroll
            for (int r = 0; r < 3; r++)
                to[r] = R[r*3+0]*tx + R[r*3+1]*ty + R[r*3+2]*tz + trans[i*3+r];
        }
    }
}

// ---------------------------------------------------------------------------
static cudaStream_t g_s1 = nullptr;
static cudaEvent_t  g_ev0, g_ev1a, g_ev1b, g_ev2, g_ev3;

extern "C" void kernel_launch(void* const* d_in, const int* in_sizes, int n_in,
                              void* d_out, int out_size)
{
    if (!g_s1) {
        cudaStreamCreateWithFlags(&g_s1, cudaStreamNonBlocking);
        cudaEventCreateWithFlags(&g_ev0,  cudaEventDisableTiming);
        cudaEventCreateWithFlags(&g_ev1a, cudaEventDisableTiming);
        cudaEventCreateWithFlags(&g_ev1b, cudaEventDisableTiming);
        cudaEventCreateWithFlags(&g_ev2,  cudaEventDisableTiming);
        cudaEventCreateWithFlags(&g_ev3,  cudaEventDisableTiming);
        cudaFuncSetAttribute(opair_tc_kernel,
                             cudaFuncAttributeMaxDynamicSharedMemorySize,
                             OPAIR_SMEM);
    }

    const float* s      = (const float*)d_in[0];
    const float* p      = (const float*)d_in[1];
    const float* rot    = (const float*)d_in[2];
    const float* trans  = (const float*)d_in[3];
    const float* mask   = (const float*)d_in[4];
    const float* w_q    = (const float*)d_in[5];
    const float* b_q    = (const float*)d_in[6];
    const float* w_kv   = (const float*)d_in[7];
    const float* b_kv   = (const float*)d_in[8];
    const float* w_qp   = (const float*)d_in[9];
    const float* b_qp   = (const float*)d_in[10];
    const float* w_kvp  = (const float*)d_in[11];
    const float* b_kvp  = (const float*)d_in[12];
    const float* w_b    = (const float*)d_in[13];
    const float* b_b    = (const float*)d_in[14];
    const float* head_w = (const float*)d_in[15];
    const float* w_o    = (const float*)d_in[16];
    const float* b_o    = (const float*)d_in[17];
    const float* ln1_g  = (const float*)d_in[18];
    const float* ln1_b  = (const float*)d_in[19];
    const float* tw1    = (const float*)d_in[20];
    const float* tb1    = (const float*)d_in[21];
    const float* tw2    = (const float*)d_in[22];
    const float* tb2    = (const float*)d_in[23];
    const float* tw3    = (const float*)d_in[24];
    const float* tb3    = (const float*)d_in[25];
    const float* ln2_g  = (const float*)d_in[26];
    const float* ln2_b  = (const float*)d_in[27];
    const float* bb_w   = (const float*)d_in[28];
    const float* bb_b   = (const float*)d_in[29];
    float* out = (float*)d_out;

    float *wcat, *bcat, *proj, *ppart, *kpk, *kppk, *vpk, *a_, *cat_,
          *part, *partB, *x2;
    cudaGetSymbolAddress((void**)&wcat, g_wcat);
    cudaGetSymbolAddress((void**)&bcat, g_bcat);
    cudaGetSymbolAddress((void**)&proj, g_proj);
    cudaGetSymbolAddress((void**)&ppart, g_ppart);
    cudaGetSymbolAddress((void**)&kpk,  g_kpack);
    cudaGetSymbolAddress((void**)&kppk, g_kppack);
    cudaGetSymbolAddress((void**)&vpk,  g_vpack);
    cudaGetSymbolAddress((void**)&a_,   g_att);
    cudaGetSymbolAddress((void**)&cat_, g_cat);
    cudaGetSymbolAddress((void**)&part, g_part);
    cudaGetSymbolAddress((void**)&partB, g_partB);
    cudaGetSymbolAddress((void**)&x2,   g_x2);

    const long long SPC = (long long)NN * CS;

    // ---- fork: bias planes on side stream, split into two i-halves --------
    cudaEventRecord(g_ev0, 0);
    cudaStreamWaitEvent(g_s1, g_ev0, 0);
    bias_kernel<<<512, 256, 0, g_s1>>>(p, w_b, b_b, a_, 0);
    cudaEventRecord(g_ev1a, g_s1);
    bias_kernel<<<512, 256, 0, g_s1>>>(p, w_b, b_b, a_, 256);
    cudaEventRecord(g_ev1b, g_s1);

    // ---- main: projections (split-K 2), fused reduce+rotate+pack ----------
    pack_w_kernel<<<(CS * LDP / 4 + LDP / 4 + 255) / 256, 256>>>(
        w_q, b_q, w_kv, b_kv, w_qp, b_qp, w_kvp, b_kvp, wcat, bcat);
    gemm64_kernel<<<dim3(LDP / 64, 8, 2), 128>>>(
        s, CS, 0, 192,
        wcat, LDP, 0, (long long)192 * LDP,
        nullptr,
        ppart, LDP, 0, (long long)NN * LDP,
        192, 2, nullptr, 0, 0, 0);
    {
        const int TOT = NN*48 + HDS*NN*4*3 + HDS*NN*8 + NN*48;
        rotpack_kernel<<<(TOT + 255) / 256, 256>>>(ppart, bcat, rot, trans,
                                                   proj, kpk, kppk, vpk);
    }

    // pipelined logits: first i-half as soon as bias half 1 is done
    cudaStreamWaitEvent(0, g_ev1a, 0);
    logits_softmax_kernel<<<dim3(32, HDS), 256>>>(proj, kpk, kppk, mask,
                                                  head_w, a_, 0);
    cudaStreamWaitEvent(0, g_ev1b, 0);
    logits_softmax_kernel<<<dim3(32, HDS), 256>>>(proj, kpk, kppk, mask,
                                                  head_w, a_, 256);

    // ---- fork: opair + w_o-high-K on side stream ---------------------------
    cudaEventRecord(g_ev2, 0);
    cudaStreamWaitEvent(g_s1, g_ev2, 0);
    opair_tc_kernel<<<NN, 128, OPAIR_SMEM, g_s1>>>(a_, p, cat_);
    gemm64_kernel<<<dim3(6, 8, 2), 128, 0, g_s1>>>(
        cat_ + 576, 2112, 0, 768,
        w_o + 576 * CS, CS, 0, (long long)768 * CS,
        nullptr,
        part + SPC, CS, 0, SPC,
        768, 2, nullptr, 0, 0, 0);
    cudaEventRecord(g_ev3, g_s1);

    // main: fused ov GEMM + postproc, then w_o low-K
    ovgemm_kernel<<<dim3(1, 8, HDS), 128>>>(a_, vpk, rot, trans, cat_);
    gemm64_kernel<<<dim3(6, 8, 1), 128>>>(
        cat_, 2112, 0, 0,
        w_o, CS, 0, 0,
        nullptr,
        part, CS, 0, 0,
        576, 1, nullptr, 0, 0, 0);
    cudaStreamWaitEvent(0, g_ev3, 0);

    // ---- reduce + residual + LN1 -------------------------------------------
    reduce_ln_kernel<<<NN, 128>>>(part, b_o, s, ln1_g, ln1_b, x2);

    // ---- transition MLP: reduces fused into next GEMM's A-staging ----------
    gemm64_kernel<<<dim3(6, 8, 3), 128>>>(
        x2, CS, 0, 128,
        tw1, CS, 0, (long long)128 * CS,
        nullptr,
        partB, CS, 0, SPC,
        128, 3, nullptr, 0, 0, 0);
    gemm64_kernel<<<dim3(6, 8, 3), 128>>>(
        partB, CS, 0, 128,
        tw2, CS, 0, (long long)128 * CS,
        nullptr,
        part, CS, 0, SPC,
        128, 3, tb1, SPC, 128, 1);
    gemm64_kernel<<<dim3(6, 8, 3), 128>>>(
        part, CS, 0, 128,
        tw3, CS, 0, (long long)128 * CS,
        nullptr,
        partB, CS, 0, SPC,
        128, 3, tb2, SPC, 128, 1);

    // ---- reduce + residual + LN2 + backbone update --------------------------
    lnbb_kernel<<<NN, 128>>>(partB, tb3, x2, ln2_g, ln2_b,
                             bb_w, bb_b, rot, trans, out);
}

// round 14
// speedup vs baseline: 1.1435x; 1.0801x over previous
#include <cuda_runtime.h>
#include <math.h>

// ---------------------------------------------------------------------------
// StructureLayer (IPA) — B=1, N=512, H=12, C_S=384, C_P=128, C_H=16,
// P_QK=4, P_V=8.  Output: [ s2 (512*384) | rot_new (512*9) | trans_new (512*3) ]
// ---------------------------------------------------------------------------

#define NN 512
#define CS 384
#define CP 128
#define HDS 12

// proj column layout: [ q(192) | kv(384) | qp(144) | kvp(432) ]  = 1152
#define LDP 1152
#define OFF_Q   0
#define OFF_KV  192
#define OFF_QP  576
#define OFF_KVP 720

#define SQK 0.14433756729740643f    // sqrt(1/48)
#define SB  0.5773502691896258f     // sqrt(1/3)
#define SHW 0.13608276348795434f    // sqrt(1/54)

// opair_tc dynamic smem: As 512*17 u32 + Bs 64*132 u32
#define OPAIR_SMEM ((512 * 17 + 64 * 132) * 4)

// ---- scratch (device globals) ----------------------------------------------
__device__ float g_proj[NN * LDP];       // only q / qp sections used
__device__ float g_ppart[4 * NN * LDP];  // proj split-K partials
__device__ float g_kpack[HDS * NN * 16];
__device__ float g_kppack[HDS * NN * 12];
__device__ float g_vpack[HDS * NN * 64]; // [h][j][ v(16) | vp(24) | pad=0 ]
__device__ float g_att[HDS * NN * NN];   // bias planes, then probs [h][i][j]
__device__ float g_cat[NN * 2112];
__device__ float g_part[6 * NN * CS];    // split-K partials (A)
__device__ float g_partB[6 * NN * CS];   // split-K partials (B)
__device__ float g_x2[NN * CS];

// ---------------------------------------------------------------------------
// tf32 helpers
// ---------------------------------------------------------------------------
__device__ __forceinline__ unsigned cvt_tf32(float x)
{
    unsigned r;
    asm("cvt.rna.tf32.f32 %0, %1;" : "=r"(r) : "f"(x));
    return r;
}

__device__ __forceinline__ void mma_tf32(float* d, const unsigned* a,
                                         const unsigned* b)
{
    asm volatile(
        "mma.sync.aligned.m16n8k8.row.col.f32.tf32.tf32.f32 "
        "{%0,%1,%2,%3}, {%4,%5,%6,%7}, {%8,%9}, {%0,%1,%2,%3};\n"
        : "+f"(d[0]), "+f"(d[1]), "+f"(d[2]), "+f"(d[3])
        : "r"(a[0]), "r"(a[1]), "r"(a[2]), "r"(a[3]),
          "r"(b[0]), "r"(b[1]));
}

// A-load: optionally reduce np split-K partials + bias + relu on the fly.
__device__ __forceinline__ float4 ldA4(const float* p,
                                       const float* abias, int bcol,
                                       long long SP, int arelu, int np)
{
    float4 v = *(const float4*)p;
    if (abias) {
        for (int sidx = 1; sidx < np; sidx++) {
            float4 vs = *(const float4*)(p + sidx * SP);
            v.x += vs.x; v.y += vs.y; v.z += vs.z; v.w += vs.w;
        }
        float4 bb = *(const float4*)(abias + bcol);
        v.x += bb.x; v.y += bb.y; v.z += bb.z; v.w += bb.w;
        if (arelu) {
            v.x = fmaxf(v.x, 0.f); v.y = fmaxf(v.y, 0.f);
            v.z = fmaxf(v.z, 0.f); v.w = fmaxf(v.w, 0.f);
        }
    }
    return v;
}

// ---------------------------------------------------------------------------
// tf32 tensor-core GEMM: 64x64 tile, 128 threads, double-buffered smem.
// z = zb*KS + zk (batch x split-K).
//  - abias != nullptr: fused A-side np-partial reduce + bias + relu.
//  - bmode == 1: B read directly from 4 packed projection weights
//    (B=w_q ld192 | B2=w_kv ld384 | B3=w_qp ld144 | B4=w_kvp ld432),
//    column selected per-thread once; sBk = k-row offset per split.
// ---------------------------------------------------------------------------
__global__ void __launch_bounds__(128)
gemm64_kernel(const float* __restrict__ A, int lda, long long sAz, long long sAk,
              const float* __restrict__ B, int ldb, long long sBz, long long sBk,
              const float* __restrict__ B2, const float* __restrict__ B3,
              const float* __restrict__ B4, int bmode,
              const float* __restrict__ bias,
              float* __restrict__ C, int ldc, long long sCz, long long sCk,
              int K, int KS,
              const float* __restrict__ abias, long long aSP, int aKoff,
              int arelu, int anp)
{
    const int zb = blockIdx.z / KS, zk = blockIdx.z % KS;
    A += (size_t)zb * (size_t)sAz + (size_t)zk * (size_t)sAk;
    C += (size_t)zb * (size_t)sCz + (size_t)zk * (size_t)sCk;
    const int azoff = zk * aKoff;

    __shared__ __align__(16) unsigned As[2][16][72];
    __shared__ __align__(16) unsigned Bs[2][16][72];

    const int bm = blockIdx.y * 64, bn = blockIdx.x * 64;
    const int tid = threadIdx.x;
    const int lane = tid & 31, warp = tid >> 5;
    const int g = lane >> 2, t4 = lane & 3;
    const int wm = (warp >> 1) * 32, wn = (warp & 1) * 32;

    const int ar = tid >> 2, ak = (tid & 3) * 4;
    const int br = tid >> 4, bc = (tid & 15) * 4;

    // resolve B source pointer / leading dim / base row for this thread
    const float* Bp;
    int ldbp, brow0 = 0;
    if (bmode) {
        brow0 = zk * (int)sBk;
        int col = bn + bc;
        if      (col < 192) { Bp = B  + col;         ldbp = 192; }
        else if (col < 576) { Bp = B2 + (col - 192); ldbp = 384; }
        else if (col < 720) { Bp = B3 + (col - 576); ldbp = 144; }
        else                { Bp = B4 + (col - 720); ldbp = 432; }
    } else {
        Bp = B + (size_t)zb * (size_t)sBz + (size_t)zk * (size_t)sBk + bn + bc;
        ldbp = ldb;
    }

    const float* Ab = A + (size_t)bm * lda;

    float4 ra0, ra1, rb0, rb1;
    ra0 = ldA4(Ab + (size_t)ar * lda + ak, abias, azoff + ak, aSP, arelu, anp);
    ra1 = ldA4(Ab + (size_t)(ar + 32) * lda + ak, abias, azoff + ak, aSP, arelu, anp);
    rb0 = *(const float4*)(Bp + (size_t)(brow0 + br) * ldbp);
    rb1 = *(const float4*)(Bp + (size_t)(brow0 + br + 8) * ldbp);

    As[0][ak+0][ar] = cvt_tf32(ra0.x); As[0][ak+1][ar] = cvt_tf32(ra0.y);
    As[0][ak+2][ar] = cvt_tf32(ra0.z); As[0][ak+3][ar] = cvt_tf32(ra0.w);
    As[0][ak+0][ar+32] = cvt_tf32(ra1.x); As[0][ak+1][ar+32] = cvt_tf32(ra1.y);
    As[0][ak+2][ar+32] = cvt_tf32(ra1.z); As[0][ak+3][ar+32] = cvt_tf32(ra1.w);
    {
        uint4 u0 = make_uint4(cvt_tf32(rb0.x), cvt_tf32(rb0.y),
                              cvt_tf32(rb0.z), cvt_tf32(rb0.w));
        uint4 u1 = make_uint4(cvt_tf32(rb1.x), cvt_tf32(rb1.y),
                              cvt_tf32(rb1.z), cvt_tf32(rb1.w));
        *(uint4*)&Bs[0][br][bc]     = u0;
        *(uint4*)&Bs[0][br + 8][bc] = u1;
    }
    __syncthreads();

    float acc[2][4][4];
    #pragma unroll
    for (int mt = 0; mt < 2; mt++)
        #pragma unroll
        for (int nt = 0; nt < 4; nt++)
            #pragma unroll
            for (int r = 0; r < 4; r++) acc[mt][nt][r] = 0.f;

    int buf = 0;
    for (int k0 = 0; k0 < K; k0 += 16) {
        const bool more = (k0 + 16) < K;
        if (more) {
            int kc = k0 + 16 + ak;
            ra0 = ldA4(Ab + (size_t)ar * lda + kc, abias, azoff + kc, aSP, arelu, anp);
            ra1 = ldA4(Ab + (size_t)(ar + 32) * lda + kc, abias, azoff + kc, aSP, arelu, anp);
            rb0 = *(const float4*)(Bp + (size_t)(brow0 + k0 + 16 + br) * ldbp);
            rb1 = *(const float4*)(Bp + (size_t)(brow0 + k0 + 16 + br + 8) * ldbp);
        }
        #pragma unroll
        for (int kk = 0; kk < 16; kk += 8) {
            unsigned af[2][4], bf[4][2];
            #pragma unroll
            for (int mt = 0; mt < 2; mt++) {
                int m0 = wm + mt * 16 + g;
                af[mt][0] = As[buf][kk + t4][m0];
                af[mt][1] = As[buf][kk + t4][m0 + 8];
                af[mt][2] = As[buf][kk + 4 + t4][m0];
                af[mt][3] = As[buf][kk + 4 + t4][m0 + 8];
            }
            #pragma unroll
            for (int nt = 0; nt < 4; nt++) {
                int n0 = wn + nt * 8 + g;
                bf[nt][0] = Bs[buf][kk + t4][n0];
                bf[nt][1] = Bs[buf][kk + 4 + t4][n0];
            }
            #pragma unroll
            for (int mt = 0; mt < 2; mt++)
                #pragma unroll
                for (int nt = 0; nt < 4; nt++)
                    mma_tf32(acc[mt][nt], af[mt], bf[nt]);
        }
        if (more) {
            buf ^= 1;
            __syncthreads();
            As[buf][ak+0][ar] = cvt_tf32(ra0.x); As[buf][ak+1][ar] = cvt_tf32(ra0.y);
            As[buf][ak+2][ar] = cvt_tf32(ra0.z); As[buf][ak+3][ar] = cvt_tf32(ra0.w);
            As[buf][ak+0][ar+32] = cvt_tf32(ra1.x); As[buf][ak+1][ar+32] = cvt_tf32(ra1.y);
            As[buf][ak+2][ar+32] = cvt_tf32(ra1.z); As[buf][ak+3][ar+32] = cvt_tf32(ra1.w);
            uint4 u0 = make_uint4(cvt_tf32(rb0.x), cvt_tf32(rb0.y),
                                  cvt_tf32(rb0.z), cvt_tf32(rb0.w));
            uint4 u1 = make_uint4(cvt_tf32(rb1.x), cvt_tf32(rb1.y),
                                  cvt_tf32(rb1.z), cvt_tf32(rb1.w));
            *(uint4*)&Bs[buf][br][bc]     = u0;
            *(uint4*)&Bs[buf][br + 8][bc] = u1;
            __syncthreads();
        }
    }

    #pragma unroll
    for (int mt = 0; mt < 2; mt++) {
        int row0 = bm + wm + mt * 16 + g;
        #pragma unroll
        for (int nt = 0; nt < 4; nt++) {
            int col = bn + wn + nt * 8 + t4 * 2;
            float b0 = 0.f, b1 = 0.f;
            if (bias) { b0 = bias[col]; b1 = bias[col + 1]; }
            float2 v0 = make_float2(acc[mt][nt][0] + b0, acc[mt][nt][1] + b1);
            float2 v1 = make_float2(acc[mt][nt][2] + b0, acc[mt][nt][3] + b1);
            *(float2*)(C + (size_t)row0 * ldc + col)       = v0;
            *(float2*)(C + (size_t)(row0 + 8) * ldc + col) = v1;
        }
    }
}

// ---------------------------------------------------------------------------
// bias planes: att[h][i][j] = (p[i,j,:]·w_b[:,h] + b_b[h]) * sqrt(1/3)
// ibase: starting residue row (for i-split pipelining).
// ---------------------------------------------------------------------------
__global__ void bias_kernel(const float* __restrict__ p,
                            const float* __restrict__ w_b,
                            const float* __restrict__ b_b,
                            float* __restrict__ att, int ibase)
{
    __shared__ float wbt[HDS][CP];
    __shared__ float bbs[HDS];
    const int tid = threadIdx.x;
    #pragma unroll
    for (int k = 0; k < 6; k++) {
        int e = tid + k * 256;
        int h = e / CP, c = e % CP;
        wbt[h][c] = w_b[c * HDS + h];
    }
    if (tid < HDS) bbs[tid] = b_b[tid];
    __syncthreads();

    const int gw = blockIdx.x * 8 + (tid >> 5);
    const int lane = tid & 31;
    const int i = ibase + (gw >> 4);
    const int j = ((gw & 15) << 5) + lane;

    float acc[HDS];
    #pragma unroll
    for (int h = 0; h < HDS; h++) acc[h] = 0.f;

    const float4* prow = (const float4*)(p + ((size_t)i * NN + j) * CP);
    #pragma unroll 4
    for (int c4 = 0; c4 < 32; c4++) {
        float4 pv = prow[c4];
        #pragma unroll
        for (int h = 0; h < HDS; h++) {
            float4 wv = ((const float4*)&wbt[h][0])[c4];
            acc[h] = fmaf(pv.x, wv.x,
                     fmaf(pv.y, wv.y,
                     fmaf(pv.z, wv.z,
                     fmaf(pv.w, wv.w, acc[h]))));
        }
    }
    #pragma unroll
    for (int h = 0; h < HDS; h++)
        att[((size_t)(h * NN) + i) * NN + j] = (acc[h] + bbs[h]) * SB;
}

// ---------------------------------------------------------------------------
// ov GEMM (att @ [v|vp], per-head) with fused postproc epilogue:
// writes o / rotated-op / norms directly into cat.  grid (1, 8, HDS).
// ---------------------------------------------------------------------------
__global__ void __launch_bounds__(128)
ovgemm_kernel(const float* __restrict__ att,
              const float* __restrict__ vpk,
              const float* __restrict__ rot,
              const float* __restrict__ trans,
              float* __restrict__ cat)
{
    const int h = blockIdx.z;
    const float* A = att + (size_t)h * NN * NN;
    const float* B = vpk + (size_t)h * NN * 64;

    __shared__ __align__(16) unsigned As[2][16][72];
    __shared__ __align__(16) unsigned Bs[2][16][72];
    __shared__ float sm[64][41];

    const int bm = blockIdx.y * 64;
    const int tid = threadIdx.x;
    const int lane = tid & 31, warp = tid >> 5;
    const int g = lane >> 2, t4 = lane & 3;
    const int wm = (warp >> 1) * 32, wn = (warp & 1) * 32;

    const int ar = tid >> 2, ak = (tid & 3) * 4;
    const int br = tid >> 4, bc = (tid & 15) * 4;

    const float* Ab = A + (size_t)bm * NN;

    float4 ra0, ra1, rb0, rb1;
    ra0 = *(const float4*)(Ab + (size_t)ar * NN + ak);
    ra1 = *(const float4*)(Ab + (size_t)(ar + 32) * NN + ak);
    rb0 = *(const float4*)(B + (size_t)br * 64 + bc);
    rb1 = *(const float4*)(B + (size_t)(br + 8) * 64 + bc);

    As[0][ak+0][ar] = cvt_tf32(ra0.x); As[0][ak+1][ar] = cvt_tf32(ra0.y);
    As[0][ak+2][ar] = cvt_tf32(ra0.z); As[0][ak+3][ar] = cvt_tf32(ra0.w);
    As[0][ak+0][ar+32] = cvt_tf32(ra1.x); As[0][ak+1][ar+32] = cvt_tf32(ra1.y);
    As[0][ak+2][ar+32] = cvt_tf32(ra1.z); As[0][ak+3][ar+32] = cvt_tf32(ra1.w);
    {
        uint4 u0 = make_uint4(cvt_tf32(rb0.x), cvt_tf32(rb0.y),
                              cvt_tf32(rb0.z), cvt_tf32(rb0.w));
        uint4 u1 = make_uint4(cvt_tf32(rb1.x), cvt_tf32(rb1.y),
                              cvt_tf32(rb1.z), cvt_tf32(rb1.w));
        *(uint4*)&Bs[0][br][bc]     = u0;
        *(uint4*)&Bs[0][br + 8][bc] = u1;
    }
    __syncthreads();

    float acc[2][4][4];
    #pragma unroll
    for (int mt = 0; mt < 2; mt++)
        #pragma unroll
        for (int nt = 0; nt < 4; nt++)
            #pragma unroll
            for (int r = 0; r < 4; r++) acc[mt][nt][r] = 0.f;

    int buf = 0;
    for (int k0 = 0; k0 < NN; k0 += 16) {
        const bool more = (k0 + 16) < NN;
        if (more) {
            ra0 = *(const float4*)(Ab + (size_t)ar * NN + k0 + 16 + ak);
            ra1 = *(const float4*)(Ab + (size_t)(ar + 32) * NN + k0 + 16 + ak);
            rb0 = *(const float4*)(B + (size_t)(k0 + 16 + br) * 64 + bc);
            rb1 = *(const float4*)(B + (size_t)(k0 + 16 + br + 8) * 64 + bc);
        }
        #pragma unroll
        for (int kk = 0; kk < 16; kk += 8) {
            unsigned af[2][4], bf[4][2];
            #pragma unroll
            for (int mt = 0; mt < 2; mt++) {
                int m0 = wm + mt * 16 + g;
                af[mt][0] = As[buf][kk + t4][m0];
                af[mt][1] = As[buf][kk + t4][m0 + 8];
                af[mt][2] = As[buf][kk + 4 + t4][m0];
                af[mt][3] = As[buf][kk + 4 + t4][m0 + 8];
            }
            #pragma unroll
            for (int nt = 0; nt < 4; nt++) {
                int n0 = wn + nt * 8 + g;
                bf[nt][0] = Bs[buf][kk + t4][n0];
                bf[nt][1] = Bs[buf][kk + 4 + t4][n0];
            }
            #pragma unroll
            for (int mt = 0; mt < 2; mt++)
                #pragma unroll
                for (int nt = 0; nt < 4; nt++)
                    mma_tf32(acc[mt][nt], af[mt], bf[nt]);
        }
        if (more) {
            buf ^= 1;
            __syncthreads();
            As[buf][ak+0][ar] = cvt_tf32(ra0.x); As[buf][ak+1][ar] = cvt_tf32(ra0.y);
            As[buf][ak+2][ar] = cvt_tf32(ra0.z); As[buf][ak+3][ar] = cvt_tf32(ra0.w);
            As[buf][ak+0][ar+32] = cvt_tf32(ra1.x); As[buf][ak+1][ar+32] = cvt_tf32(ra1.y);
            As[buf][ak+2][ar+32] = cvt_tf32(ra1.z); As[buf][ak+3][ar+32] = cvt_tf32(ra1.w);
            uint4 u0 = make_uint4(cvt_tf32(rb0.x), cvt_tf32(rb0.y),
                                  cvt_tf32(rb0.z), cvt_tf32(rb0.w));
            uint4 u1 = make_uint4(cvt_tf32(rb1.x), cvt_tf32(rb1.y),
                                  cvt_tf32(rb1.z), cvt_tf32(rb1.w));
            *(uint4*)&Bs[buf][br][bc]     = u0;
            *(uint4*)&Bs[buf][br + 8][bc] = u1;
            __syncthreads();
        }
    }

    #pragma unroll
    for (int mt = 0; mt < 2; mt++) {
        int r0 = wm + mt * 16 + g;
        #pragma unroll
        for (int nt = 0; nt < 4; nt++) {
            int col = wn + nt * 8 + t4 * 2;
            if (col < 40) {
                sm[r0][col]       = acc[mt][nt][0];
                sm[r0][col + 1]   = acc[mt][nt][1];
                sm[r0 + 8][col]     = acc[mt][nt][2];
                sm[r0 + 8][col + 1] = acc[mt][nt][3];
            }
        }
    }
    __syncthreads();

    #pragma unroll
    for (int l = 0; l < 8; l++) {
        int e = tid + l * 128;
        int r = e >> 4, c = e & 15;
        cat[(size_t)(bm + r) * 2112 + h * 16 + c] = sm[r][c];
    }
    #pragma unroll
    for (int l = 0; l < 4; l++) {
        int e = tid + l * 128;
        int r = e >> 3, pp = e & 7;
        int i = bm + r;
        float vx = sm[r][16 + pp*3 + 0] - trans[i*3 + 0];
        float vy = sm[r][16 + pp*3 + 1] - trans[i*3 + 1];
        float vz = sm[r][16 + pp*3 + 2] - trans[i*3 + 2];
        const float* R = rot + i * 9;
        float ox = R[0]*vx + R[3]*vy + R[6]*vz;
        float oy = R[1]*vx + R[4]*vy + R[7]*vz;
        float oz = R[2]*vx + R[5]*vy + R[8]*vz;
        float* ci = cat + (size_t)i * 2112;
        ci[192 + h*24 + pp*3 + 0] = ox;
        ci[192 + h*24 + pp*3 + 1] = oy;
        ci[192 + h*24 + pp*3 + 2] = oz;
        ci[480 + h*8 + pp] = sqrtf(ox*ox + oy*oy + oz*oz + 1e-8f);
    }
}

// ---------------------------------------------------------------------------
// o_pair via tensor cores: per-i block computes (16x512)@(512x128)
// ---------------------------------------------------------------------------
extern __shared__ unsigned opair_smem[];
__global__ void __launch_bounds__(128)
opair_tc_kernel(const float* __restrict__ att,
                const float* __restrict__ p,
                float* __restrict__ cat)
{
    const int i = blockIdx.x;
    unsigned* As = opair_smem;                 // [j][h] stride 17
    unsigned* Bs = opair_smem + 512 * 17;      // [jj][c] stride 132
    const int tid = threadIdx.x;

    for (int idx = tid; idx < HDS * NN; idx += 128) {
        int j = idx & 511, h = idx >> 9;
        As[j * 17 + h] = cvt_tf32(att[((size_t)(h * NN) + i) * NN + j]);
    }
    for (int idx = tid; idx < 4 * NN; idx += 128) {
        int j = idx & 511, h = 12 + (idx >> 9);
        As[j * 17 + h] = 0u;
    }

    const int lane = tid & 31, warp = tid >> 5;
    const int g = lane >> 2, t4 = lane & 3;
    const int wn = warp * 32;

    float acc[4][4];
    #pragma unroll
    for (int nt = 0; nt < 4; nt++)
        #pragma unroll
        for (int r = 0; r < 4; r++) acc[nt][r] = 0.f;

    const float4* pi4 = (const float4*)(p + (size_t)i * NN * CP);

    for (int j0 = 0; j0 < NN; j0 += 64) {
        __syncthreads();
        #pragma unroll
        for (int l = 0; l < 16; l++) {
            int e = tid + l * 128;
            int jj = e >> 5, c4 = e & 31;
            float4 v = pi4[(size_t)(j0 + jj) * 32 + c4];
            uint4 u = make_uint4(cvt_tf32(v.x), cvt_tf32(v.y),
                                 cvt_tf32(v.z), cvt_tf32(v.w));
            *(uint4*)&Bs[jj * 132 + c4 * 4] = u;
        }
        __syncthreads();
        #pragma unroll
        for (int ks = 0; ks < 8; ks++) {
            unsigned af[4];
            int kg = (j0 + ks * 8 + t4) * 17;
            int kg4 = (j0 + ks * 8 + 4 + t4) * 17;
            af[0] = As[kg + g];
            af[1] = As[kg + g + 8];
            af[2] = As[kg4 + g];
            af[3] = As[kg4 + g + 8];
            #pragma unroll
            for (int nt = 0; nt < 4; nt++) {
                unsigned bf[2];
                int n0 = wn + nt * 8 + g;
                bf[0] = Bs[(ks * 8 + t4) * 132 + n0];
                bf[1] = Bs[(ks * 8 + 4 + t4) * 132 + n0];
                mma_tf32(acc[nt], af, bf);
            }
        }
    }

    float* dst = cat + (size_t)i * 2112 + 576;
    #pragma unroll
    for (int nt = 0; nt < 4; nt++) {
        int col = wn + nt * 8 + t4 * 2;
        dst[g * 128 + col]     = acc[nt][0];
        dst[g * 128 + col + 1] = acc[nt][1];
        if (g + 8 < HDS) {
            dst[(g + 8) * 128 + col]     = acc[nt][2];
            dst[(g + 8) * 128 + col + 1] = acc[nt][3];
        }
    }
}

// ---------------------------------------------------------------------------
// Fused proj split-K reduce (4 partials) + bias (direct from b_q/b_kv/b_qp/
// b_kvp) + rotate + repack.
// ---------------------------------------------------------------------------
__global__ void rotpack_kernel(const float* __restrict__ ppart,
                               const float* __restrict__ b_q,
                               const float* __restrict__ b_kv,
                               const float* __restrict__ b_qp,
                               const float* __restrict__ b_kvp,
                               const float* __restrict__ rot,
                               const float* __restrict__ trans,
                               float* __restrict__ proj,
                               float* __restrict__ kpack,
                               float* __restrict__ kppack,
                               float* __restrict__ vpack)
{
    const long long SP = (long long)NN * LDP;
    const int S0 = NN * 48;
    const int S1 = S0 + HDS * NN * 4;
    const int S2 = S1 + HDS * NN * 4;
    const int S3 = S2 + HDS * NN * 4;
    const int S4 = S3 + HDS * NN * 8;
    const int S5 = S4 + NN * 48;
    int idx = blockIdx.x * blockDim.x + threadIdx.x;

    if (idx < S0) {
        int j = idx / 48, c = (idx % 48) * 4;
        const float* p0 = ppart + (size_t)j * LDP + c;
        float4 a = *(const float4*)p0;
        float4 b1 = *(const float4*)(p0 + SP);
        float4 b2 = *(const float4*)(p0 + 2 * SP);
        float4 b3 = *(const float4*)(p0 + 3 * SP);
        float4 bb = *(const float4*)(b_q + c);
        *(float4*)(proj + (size_t)j * LDP + c) =
            make_float4(a.x+b1.x+b2.x+b3.x+bb.x, a.y+b1.y+b2.y+b3.y+bb.y,
                        a.z+b1.z+b2.z+b3.z+bb.z, a.w+b1.w+b2.w+b3.w+bb.w);
    } else if (idx < S1) {
        int t = idx - S0;
        int c = (t & 3) * 4, j = (t >> 2) & 511, h = t >> 11;
        int col = OFF_KV + h * 32 + c;
        const float* p0 = ppart + (size_t)j * LDP + col;
        float4 a = *(const float4*)p0;
        float4 b1 = *(const float4*)(p0 + SP);
        float4 b2 = *(const float4*)(p0 + 2 * SP);
        float4 b3 = *(const float4*)(p0 + 3 * SP);
        float4 bb = *(const float4*)(b_kv + h * 32 + c);
        *(float4*)(kpack + (((size_t)h * NN) + j) * 16 + c) =
            make_float4(a.x+b1.x+b2.x+b3.x+bb.x, a.y+b1.y+b2.y+b3.y+bb.y,
                        a.z+b1.z+b2.z+b3.z+bb.z, a.w+b1.w+b2.w+b3.w+bb.w);
    } else if (idx < S2) {
        int t = idx - S1;
        int c = (t & 3) * 4, j = (t >> 2) & 511, h = t >> 11;
        int col = OFF_KV + h * 32 + 16 + c;
        const float* p0 = ppart + (size_t)j * LDP + col;
        float4 a = *(const float4*)p0;
        float4 b1 = *(const float4*)(p0 + SP);
        float4 b2 = *(const float4*)(p0 + 2 * SP);
        float4 b3 = *(const float4*)(p0 + 3 * SP);
        float4 bb = *(const float4*)(b_kv + h * 32 + 16 + c);
        *(float4*)(vpack + (((size_t)h * NN) + j) * 64 + c) =
            make_float4(a.x+b1.x+b2.x+b3.x+bb.x, a.y+b1.y+b2.y+b3.y+bb.y,
                        a.z+b1.z+b2.z+b3.z+bb.z, a.w+b1.w+b2.w+b3.w+bb.w);
    } else if (idx < S4) {
        int t = idx - S2;
        int pp, j, h;
        float* dst;
        if (t < HDS * NN * 4) {
            pp = t & 3; j = (t >> 2) & 511; h = t >> 11;
            dst = kppack + (((size_t)h * NN) + j) * 12 + pp * 3;
        } else {
            t -= HDS * NN * 4;
            int vp = t & 7; j = (t >> 3) & 511; h = t >> 12;
            pp = 4 + vp;
            dst = vpack + (((size_t)h * NN) + j) * 64 + 16 + vp * 3;
        }
        int col = OFF_KVP + h * 36 + pp * 3;
        int lcol = h * 36 + pp * 3;
        const float* p0 = ppart + (size_t)j * LDP + col;
        float x = p0[0] + p0[SP+0] + p0[2*SP+0] + p0[3*SP+0] + b_kvp[lcol + 0];
        float y = p0[1] + p0[SP+1] + p0[2*SP+1] + p0[3*SP+1] + b_kvp[lcol + 1];
        float z = p0[2] + p0[SP+2] + p0[2*SP+2] + p0[3*SP+2] + b_kvp[lcol + 2];
        const float* R = rot + j * 9;
        const float* tr = trans + j * 3;
        dst[0] = R[0]*x + R[1]*y + R[2]*z + tr[0];
        dst[1] = R[3]*x + R[4]*y + R[5]*z + tr[1];
        dst[2] = R[6]*x + R[7]*y + R[8]*z + tr[2];
    } else if (idx < S5) {
        int t = idx - S4;
        int pt = t % 48, j = t / 48;
        int col = OFF_QP + pt * 3;
        const float* p0 = ppart + (size_t)j * LDP + col;
        float x = p0[0] + p0[SP+0] + p0[2*SP+0] + p0[3*SP+0] + b_qp[pt*3 + 0];
        float y = p0[1] + p0[SP+1] + p0[2*SP+1] + p0[3*SP+1] + b_qp[pt*3 + 1];
        float z = p0[2] + p0[SP+2] + p0[2*SP+2] + p0[3*SP+2] + b_qp[pt*3 + 2];
        const float* R = rot + j * 9;
        const float* tr = trans + j * 3;
        float* pv = proj + (size_t)j * LDP + col;
        pv[0] = R[0]*x + R[1]*y + R[2]*z + tr[0];
        pv[1] = R[3]*x + R[4]*y + R[5]*z + tr[1];
        pv[2] = R[6]*x + R[7]*y + R[8]*z + tr[2];
    }
}

// ---------------------------------------------------------------------------
// Fused logits + softmax.  Block = (i-tile of 8, head h).  256 threads.
// ---------------------------------------------------------------------------
__global__ void logits_softmax_kernel(const float* __restrict__ proj,
                                      const float* __restrict__ kpack,
                                      const float* __restrict__ kppack,
                                      const float* __restrict__ mask,
                                      const float* __restrict__ head_w,
                                      float* __restrict__ att, int ibase)
{
    const int i0 = ibase + blockIdx.x * 8, h = blockIdx.y;
    const int tid = threadIdx.x;

    __shared__ float att_s[8][NN];
    __shared__ float kt[64][17];
    __shared__ float kpt[64][13];
    __shared__ float q_s[8][17];
    __shared__ float qp_s[8][13];
    __shared__ float m_i[8];
    __shared__ float sh_hw;

    if (tid < 128) {
        int il = tid >> 4, c = tid & 15;
        q_s[il][c] = proj[(size_t)(i0 + il) * LDP + OFF_Q + h * 16 + c];
    } else if (tid < 224) {
        int e = tid - 128;
        int il = e / 12, c = e % 12;
        qp_s[il][c] = proj[(size_t)(i0 + il) * LDP + OFF_QP + h * 12 + c];
    } else if (tid < 232) {
        m_i[tid - 224] = mask[i0 + (tid - 224)];
    } else if (tid == 232) {
        float w = head_w[h];
        float sp = fmaxf(w, 0.f) + log1pf(expf(-fabsf(w)));
        sh_hw = sp * SHW;
    }

    const float* kb  = kpack  + (size_t)(h * NN) * 16;
    const float* kpb = kppack + (size_t)(h * NN) * 12;

    const int jl = tid & 63, ig = tid >> 6;

    for (int j0 = 0; j0 < NN; j0 += 64) {
        #pragma unroll
        for (int k = 0; k < 4; k++) {
            int e = tid + k * 256;
            int r = e >> 4, c = e & 15;
            kt[r][c] = kb[(size_t)(j0 + r) * 16 + c];
        }
        #pragma unroll
        for (int k = 0; k < 3; k++) {
            int e = tid + k * 256;
            if (e < 768) {
                int r = e / 12, c = e % 12;
                kpt[r][c] = kpb[(size_t)(j0 + r) * 12 + c];
            }
        }
        __syncthreads();

        float mj = mask[j0 + jl];
        float hw = sh_hw;
        #pragma unroll
        for (int ii = 0; ii < 2; ii++) {
            int il = ig * 2 + ii;
            float qk = 0.f;
            #pragma unroll
            for (int c = 0; c < 16; c++) qk = fmaf(q_s[il][c], kt[jl][c], qk);
            float d2 = 0.f;
            #pragma unroll
            for (int d = 0; d < 12; d++) {
                float dd = qp_s[il][d] - kpt[jl][d];
                d2 = fmaf(dd, dd, d2);
            }
            float bias = att[((size_t)(h * NN) + i0 + il) * NN + j0 + jl];
            att_s[il][j0 + jl] = qk * SQK + bias - 0.5f * hw * d2
                               + (m_i[il] * mj - 1.0f) * 100000.0f;
        }
        __syncthreads();
    }

    const int w = tid >> 5, lane = tid & 31;
    float vals[16];
    float vmax = -1e30f;
    #pragma unroll
    for (int k = 0; k < 16; k++) {
        vals[k] = att_s[w][lane + 32 * k];
        vmax = fmaxf(vmax, vals[k]);
    }
    #pragma unroll
    for (int o = 16; o > 0; o >>= 1)
        vmax = fmaxf(vmax, __shfl_xor_sync(0xffffffffu, vmax, o));
    float sum = 0.f;
    #pragma unroll
    for (int k = 0; k < 16; k++) { vals[k] = expf(vals[k] - vmax); sum += vals[k]; }
    #pragma unroll
    for (int o = 16; o > 0; o >>= 1)
        sum += __shfl_xor_sync(0xffffffffu, sum, o);
    float inv = 1.0f / sum;
    float* arow = att + ((size_t)(h * NN) + i0 + w) * NN;
    #pragma unroll
    for (int k = 0; k < 16; k++)
        arow[lane + 32 * k] = vals[k] * inv;
}

// ---------------------------------------------------------------------------
// 6-way split-K reduce + bias + residual + LayerNorm.  Block/row, 128 thr.
// ---------------------------------------------------------------------------
__global__ void reduce_ln_kernel(const float* __restrict__ part,
                                 const float* __restrict__ bias,
                                 const float* __restrict__ res,
                                 const float* __restrict__ g,
                                 const float* __restrict__ b,
                                 float* __restrict__ y)
{
    __shared__ float rs[128], rs2[128];
    const int i = blockIdx.x, tid = threadIdx.x;
    const size_t SP = (size_t)NN * CS;
    float v[3];
    float sm = 0.f, sm2 = 0.f;
    #pragma unroll
    for (int k = 0; k < 3; k++) {
        int c = tid + k * 128;
        size_t o = (size_t)i * CS + c;
        float x = bias[c] + res[o];
        #pragma unroll
        for (int sl = 0; sl < 6; sl++) x += part[sl * SP + o];
        v[k] = x;
        sm += x; sm2 += x * x;
    }
    rs[tid] = sm; rs2[tid] = sm2;
    __syncthreads();
    for (int st = 64; st > 0; st >>= 1) {
        if (tid < st) { rs[tid] += rs[tid + st]; rs2[tid] += rs2[tid + st]; }
        __syncthreads();
    }
    float mean = rs[0] * (1.0f / CS);
    float var  = rs2[0] * (1.0f / CS) - mean * mean;
    float inv  = rsqrtf(var + 1e-5f);
    #pragma unroll
    for (int k = 0; k < 3; k++) {
        int c = tid + k * 128;
        y[(size_t)i * CS + c] = (v[k] - mean) * inv * g[c] + b[c];
    }
}

// ---------------------------------------------------------------------------
// Fused: 6-way reduce + bias + residual + LayerNorm2 + backbone projection
// + quaternion frame update.  Block per row, 128 threads.
// ---------------------------------------------------------------------------
__global__ void lnbb_kernel(const float* __restrict__ part,
                            const float* __restrict__ bias,
                            const float* __restrict__ res,
                            const float* __restrict__ g,
                            const float* __restrict__ b,
                            const float* __restrict__ bb_w,
                            const float* __restrict__ bb_b,
                            const float* __restrict__ rot,
                            const float* __restrict__ trans,
                            float* __restrict__ out)
{
    __shared__ float rs[128], rs2[128], ys[CS], wsm[CS * 6], u[6];
    const int i = blockIdx.x, tid = threadIdx.x;
    const size_t SP = (size_t)NN * CS;

    #pragma unroll
    for (int k = 0; k < 18; k++) wsm[tid + k * 128] = bb_w[tid + k * 128];

    float v[3];
    float sm = 0.f, sm2 = 0.f;
    #pragma unroll
    for (int k = 0; k < 3; k++) {
        int c = tid + k * 128;
        size_t o = (size_t)i * CS + c;
        float x = bias[c] + res[o];
        #pragma unroll
        for (int sl = 0; sl < 6; sl++) x += part[sl * SP + o];
        v[k] = x;
        sm += x; sm2 += x * x;
    }
    rs[tid] = sm; rs2[tid] = sm2;
    __syncthreads();
    for (int st = 64; st > 0; st >>= 1) {
        if (tid < st) { rs[tid] += rs[tid + st]; rs2[tid] += rs2[tid + st]; }
        __syncthreads();
    }
    float mean = rs[0] * (1.0f / CS);
    float var  = rs2[0] * (1.0f / CS) - mean * mean;
    float inv  = rsqrtf(var + 1e-5f);
    #pragma unroll
    for (int k = 0; k < 3; k++) {
        int c = tid + k * 128;
        float yv = (v[k] - mean) * inv * g[c] + b[c];
        ys[c] = yv;
        out[(size_t)i * CS + c] = yv;
    }
    __syncthreads();

    if (tid < 32) {
        #pragma unroll
        for (int o = 0; o < 6; o++) {
            float sum = 0.f;
            for (int c = tid; c < CS; c += 32)
                sum = fmaf(ys[c], wsm[c * 6 + o], sum);
            #pragma unroll
            for (int off = 16; off > 0; off >>= 1)
                sum += __shfl_xor_sync(0xffffffffu, sum, off);
            if (tid == 0) u[o] = sum + bb_b[o];
        }
        if (tid == 0) {
            float bx = u[0], by = u[1], bz = u[2];
            float qinv = rsqrtf(1.f + bx*bx + by*by + bz*bz);
            float qw = qinv, x = bx * qinv, y = by * qinv, z = bz * qinv;
            float Ru[9] = {
                1 - 2*(y*y + z*z), 2*(x*y - qw*z),    2*(x*z + qw*y),
                2*(x*y + qw*z),    1 - 2*(x*x + z*z), 2*(y*z - qw*x),
                2*(x*z - qw*y),    2*(y*z + qw*x),    1 - 2*(x*x + y*y)};
            const float* R = rot + i * 9;
            float* ro = out + NN * CS + i * 9;
            #pragma unroll
            for (int r = 0; r < 3; r++)
                #pragma unroll
                for (int c = 0; c < 3; c++)
                    ro[r*3+c] = R[r*3+0]*Ru[0*3+c] + R[r*3+1]*Ru[1*3+c]
                              + R[r*3+2]*Ru[2*3+c];
            float tx = u[3], ty = u[4], tz = u[5];
            float* to = out + NN * CS + NN * 9 + i * 3;
            #pragma unroll
            for (int r = 0; r < 3; r++)
                to[r] = R[r*3+0]*tx + R[r*3+1]*ty + R[r*3+2]*tz + trans[i*3+r];
        }
    }
}

// ---------------------------------------------------------------------------
static cudaStream_t g_s1 = nullptr;
static cudaEvent_t  g_ev0, g_ev1a, g_ev1b, g_ev2, g_ev3;

extern "C" void kernel_launch(void* const* d_in, const int* in_sizes, int n_in,
                              void* d_out, int out_size)
{
    if (!g_s1) {
        cudaStreamCreateWithFlags(&g_s1, cudaStreamNonBlocking);
        cudaEventCreateWithFlags(&g_ev0,  cudaEventDisableTiming);
        cudaEventCreateWithFlags(&g_ev1a, cudaEventDisableTiming);
        cudaEventCreateWithFlags(&g_ev1b, cudaEventDisableTiming);
        cudaEventCreateWithFlags(&g_ev2,  cudaEventDisableTiming);
        cudaEventCreateWithFlags(&g_ev3,  cudaEventDisableTiming);
        cudaFuncSetAttribute(opair_tc_kernel,
                             cudaFuncAttributeMaxDynamicSharedMemorySize,
                             OPAIR_SMEM);
    }

    const float* s      = (const float*)d_in[0];
    const float* p      = (const float*)d_in[1];
    const float* rot    = (const float*)d_in[2];
    const float* trans  = (const float*)d_in[3];
    const float* mask   = (const float*)d_in[4];
    const float* w_q    = (const float*)d_in[5];
    const float* b_q    = (const float*)d_in[6];
    const float* w_kv   = (const float*)d_in[7];
    const float* b_kv   = (const float*)d_in[8];
    const float* w_qp   = (const float*)d_in[9];
    const float* b_qp   = (const float*)d_in[10];
    const float* w_kvp  = (const float*)d_in[11];
    const float* b_kvp  = (const float*)d_in[12];
    const float* w_b    = (const float*)d_in[13];
    const float* b_b    = (const float*)d_in[14];
    const float* head_w = (const float*)d_in[15];
    const float* w_o    = (const float*)d_in[16];
    const float* b_o    = (const float*)d_in[17];
    const float* ln1_g  = (const float*)d_in[18];
    const float* ln1_b  = (const float*)d_in[19];
    const float* tw1    = (const float*)d_in[20];
    const float* tb1    = (const float*)d_in[21];
    const float* tw2    = (const float*)d_in[22];
    const float* tb2    = (const float*)d_in[23];
    const float* tw3    = (const float*)d_in[24];
    const float* tb3    = (const float*)d_in[25];
    const float* ln2_g  = (const float*)d_in[26];
    const float* ln2_b  = (const float*)d_in[27];
    const float* bb_w   = (const float*)d_in[28];
    const float* bb_b   = (const float*)d_in[29];
    float* out = (float*)d_out;

    float *proj, *ppart, *kpk, *kppk, *vpk, *a_, *cat_, *part, *partB, *x2;
    cudaGetSymbolAddress((void**)&proj, g_proj);
    cudaGetSymbolAddress((void**)&ppart, g_ppart);
    cudaGetSymbolAddress((void**)&kpk,  g_kpack);
    cudaGetSymbolAddress((void**)&kppk, g_kppack);
    cudaGetSymbolAddress((void**)&vpk,  g_vpack);
    cudaGetSymbolAddress((void**)&a_,   g_att);
    cudaGetSymbolAddress((void**)&cat_, g_cat);
    cudaGetSymbolAddress((void**)&part, g_part);
    cudaGetSymbolAddress((void**)&partB, g_partB);
    cudaGetSymbolAddress((void**)&x2,   g_x2);

    const long long SPC = (long long)NN * CS;

    // ---- fork: bias planes on side stream, split into two i-halves --------
    cudaEventRecord(g_ev0, 0);
    cudaStreamWaitEvent(g_s1, g_ev0, 0);
    bias_kernel<<<512, 256, 0, g_s1>>>(p, w_b, b_b, a_, 0);
    cudaEventRecord(g_ev1a, g_s1);
    bias_kernel<<<512, 256, 0, g_s1>>>(p, w_b, b_b, a_, 256);
    cudaEventRecord(g_ev1b, g_s1);

    // ---- main: projections (split-K 4, B read directly from weights) ------
    gemm64_kernel<<<dim3(LDP / 64, 8, 4), 128>>>(
        s, CS, 0, 96,
        w_q, 0, 0, 96,
        w_kv, w_qp, w_kvp, 1,
        nullptr,
        ppart, LDP, 0, (long long)NN * LDP,
        96, 4, nullptr, 0, 0, 0, 0);
    {
        const int TOT = NN*48 + HDS*NN*4*3 + HDS*NN*8 + NN*48;
        rotpack_kernel<<<(TOT + 255) / 256, 256>>>(
            ppart, b_q, b_kv, b_qp, b_kvp, rot, trans,
            proj, kpk, kppk, vpk);
    }

    // pipelined logits: first i-half as soon as bias half 1 is done
    cudaStreamWaitEvent(0, g_ev1a, 0);
    logits_softmax_kernel<<<dim3(32, HDS), 256>>>(proj, kpk, kppk, mask,
                                                  head_w, a_, 0);
    cudaStreamWaitEvent(0, g_ev1b, 0);
    logits_softmax_kernel<<<dim3(32, HDS), 256>>>(proj, kpk, kppk, mask,
                                                  head_w, a_, 256);

    // ---- fork: opair + w_o-high-K on side stream ---------------------------
    cudaEventRecord(g_ev2, 0);
    cudaStreamWaitEvent(g_s1, g_ev2, 0);
    opair_tc_kernel<<<NN, 128, OPAIR_SMEM, g_s1>>>(a_, p, cat_);
    // w_o cols 576..2111 (opair region), split-K 4 -> part slots 2..5
    gemm64_kernel<<<dim3(6, 8, 4), 128, 0, g_s1>>>(
        cat_ + 576, 2112, 0, 384,
        w_o + 576 * CS, CS, 0, (long long)384 * CS,
        nullptr, nullptr, nullptr, 0,
        nullptr,
        part + 2 * SPC, CS, 0, SPC,
        384, 4, nullptr, 0, 0, 0, 0);
    cudaEventRecord(g_ev3, g_s1);

    // main: fused ov GEMM + postproc, then w_o low-K (slots 0..1)
    ovgemm_kernel<<<dim3(1, 8, HDS), 128>>>(a_, vpk, rot, trans, cat_);
    gemm64_kernel<<<dim3(6, 8, 2), 128>>>(
        cat_, 2112, 0, 288,
        w_o, CS, 0, (long long)288 * CS,
        nullptr, nullptr, nullptr, 0,
        nullptr,
        part, CS, 0, SPC,
        288, 2, nullptr, 0, 0, 0, 0);
    cudaStreamWaitEvent(0, g_ev3, 0);

    // ---- reduce(6) + residual + LN1 ----------------------------------------
    reduce_ln_kernel<<<NN, 128>>>(part, b_o, s, ln1_g, ln1_b, x2);

    // ---- transition MLP: split-K 6, reduces fused into next GEMM ----------
    gemm64_kernel<<<dim3(6, 8, 6), 128>>>(
        x2, CS, 0, 64,
        tw1, CS, 0, (long long)64 * CS,
        nullptr, nullptr, nullptr, 0,
        nullptr,
        partB, CS, 0, SPC,
        64, 6, nullptr, 0, 0, 0, 0);
    gemm64_kernel<<<dim3(6, 8, 6), 128>>>(
        partB, CS, 0, 64,
        tw2, CS, 0, (long long)64 * CS,
        nullptr, nullptr, nullptr, 0,
        nullptr,
        part, CS, 0, SPC,
        64, 6, tb1, SPC, 64, 1, 6);
    gemm64_kernel<<<dim3(6, 8, 6), 128>>>(
        part, CS, 0, 64,
        tw3, CS, 0, (long long)64 * CS,
        nullptr, nullptr, nullptr, 0,
        nullptr,
        partB, CS, 0, SPC,
        64, 6, tb2, SPC, 64, 1, 6);

    // ---- reduce(6) + residual + LN2 + backbone update ----------------------
    lnbb_kernel<<<NN, 128>>>(partB, tb3, x2, ln2_g, ln2_b,
                             bb_w, bb_b, rot, trans, out);
}

// round 15
// speedup vs baseline: 1.1603x; 1.0147x over previous
#include <cuda_runtime.h>
#include <math.h>

// ---------------------------------------------------------------------------
// StructureLayer (IPA) — B=1, N=512, H=12, C_S=384, C_P=128, C_H=16,
// P_QK=4, P_V=8.  Output: [ s2 (512*384) | rot_new (512*9) | trans_new (512*3) ]
// ---------------------------------------------------------------------------

#define NN 512
#define CS 384
#define CP 128
#define HDS 12

// proj column layout: [ q(192) | kv(384) | qp(144) | kvp(432) ]  = 1152
#define LDP 1152
#define OFF_Q   0
#define OFF_KV  192
#define OFF_QP  576
#define OFF_KVP 720

#define SQK 0.14433756729740643f    // sqrt(1/48)
#define SB  0.5773502691896258f     // sqrt(1/3)
#define SHW 0.13608276348795434f    // sqrt(1/54)

// opair_tc dynamic smem: As 512*17 u32 + Bs 64*132 u32
#define OPAIR_SMEM ((512 * 17 + 64 * 132) * 4)
// logits dynamic smem: kt 512*17 + kpt 512*13 + att_s 8*512 + q 8*17
//                      + qp 8*13 + mask 512 + m_i 8 + hw 1
#define LOGITS_SMEM ((512*17 + 512*13 + 8*512 + 8*17 + 8*13 + 512 + 8 + 1) * 4)

// ---- scratch (device globals) ----------------------------------------------
__device__ float g_proj[NN * LDP];       // only q / qp sections used
__device__ float g_ppart[4 * NN * LDP];  // proj split-K partials
__device__ float g_kpack[HDS * NN * 16];
__device__ float g_kppack[HDS * NN * 12];
__device__ float g_vpack[HDS * NN * 64]; // [h][j][ v(16) | vp(24) | pad=0 ]
__device__ float g_att[HDS * NN * NN];   // bias planes, then probs [h][i][j]
__device__ float g_cat[NN * 2112];
__device__ float g_part[6 * NN * CS];    // split-K partials (A)
__device__ float g_partB[6 * NN * CS];   // split-K partials (B)
__device__ float g_x2[NN * CS];

// ---------------------------------------------------------------------------
// tf32 helpers
// ---------------------------------------------------------------------------
__device__ __forceinline__ unsigned cvt_tf32(float x)
{
    unsigned r;
    asm("cvt.rna.tf32.f32 %0, %1;" : "=r"(r) : "f"(x));
    return r;
}

__device__ __forceinline__ void mma_tf32(float* d, const unsigned* a,
                                         const unsigned* b)
{
    asm volatile(
        "mma.sync.aligned.m16n8k8.row.col.f32.tf32.tf32.f32 "
        "{%0,%1,%2,%3}, {%4,%5,%6,%7}, {%8,%9}, {%0,%1,%2,%3};\n"
        : "+f"(d[0]), "+f"(d[1]), "+f"(d[2]), "+f"(d[3])
        : "r"(a[0]), "r"(a[1]), "r"(a[2]), "r"(a[3]),
          "r"(b[0]), "r"(b[1]));
}

// A-load: optionally reduce np split-K partials + bias + relu on the fly.
__device__ __forceinline__ float4 ldA4(const float* p,
                                       const float* abias, int bcol,
                                       long long SP, int arelu, int np)
{
    float4 v = *(const float4*)p;
    if (abias) {
        for (int sidx = 1; sidx < np; sidx++) {
            float4 vs = *(const float4*)(p + sidx * SP);
            v.x += vs.x; v.y += vs.y; v.z += vs.z; v.w += vs.w;
        }
        float4 bb = *(const float4*)(abias + bcol);
        v.x += bb.x; v.y += bb.y; v.z += bb.z; v.w += bb.w;
        if (arelu) {
            v.x = fmaxf(v.x, 0.f); v.y = fmaxf(v.y, 0.f);
            v.z = fmaxf(v.z, 0.f); v.w = fmaxf(v.w, 0.f);
        }
    }
    return v;
}

// ---------------------------------------------------------------------------
// tf32 tensor-core GEMM: 64x64 tile, 128 threads, double-buffered smem.
// z = zb*KS + zk (batch x split-K).
//  - abias != nullptr: fused A-side np-partial reduce + bias + relu.
//  - bmode == 1: B read directly from 4 packed projection weights.
// ---------------------------------------------------------------------------
__global__ void __launch_bounds__(128)
gemm64_kernel(const float* __restrict__ A, int lda, long long sAz, long long sAk,
              const float* __restrict__ B, int ldb, long long sBz, long long sBk,
              const float* __restrict__ B2, const float* __restrict__ B3,
              const float* __restrict__ B4, int bmode,
              const float* __restrict__ bias,
              float* __restrict__ C, int ldc, long long sCz, long long sCk,
              int K, int KS,
              const float* __restrict__ abias, long long aSP, int aKoff,
              int arelu, int anp)
{
    const int zb = blockIdx.z / KS, zk = blockIdx.z % KS;
    A += (size_t)zb * (size_t)sAz + (size_t)zk * (size_t)sAk;
    C += (size_t)zb * (size_t)sCz + (size_t)zk * (size_t)sCk;
    const int azoff = zk * aKoff;

    __shared__ __align__(16) unsigned As[2][16][72];
    __shared__ __align__(16) unsigned Bs[2][16][72];

    const int bm = blockIdx.y * 64, bn = blockIdx.x * 64;
    const int tid = threadIdx.x;
    const int lane = tid & 31, warp = tid >> 5;
    const int g = lane >> 2, t4 = lane & 3;
    const int wm = (warp >> 1) * 32, wn = (warp & 1) * 32;

    const int ar = tid >> 2, ak = (tid & 3) * 4;
    const int br = tid >> 4, bc = (tid & 15) * 4;

    // resolve B source pointer / leading dim / base row for this thread
    const float* Bp;
    int ldbp, brow0 = 0;
    if (bmode) {
        brow0 = zk * (int)sBk;
        int col = bn + bc;
        if      (col < 192) { Bp = B  + col;         ldbp = 192; }
        else if (col < 576) { Bp = B2 + (col - 192); ldbp = 384; }
        else if (col < 720) { Bp = B3 + (col - 576); ldbp = 144; }
        else                { Bp = B4 + (col - 720); ldbp = 432; }
    } else {
        Bp = B + (size_t)zb * (size_t)sBz + (size_t)zk * (size_t)sBk + bn + bc;
        ldbp = ldb;
    }

    const float* Ab = A + (size_t)bm * lda;

    float4 ra0, ra1, rb0, rb1;
    ra0 = ldA4(Ab + (size_t)ar * lda + ak, abias, azoff + ak, aSP, arelu, anp);
    ra1 = ldA4(Ab + (size_t)(ar + 32) * lda + ak, abias, azoff + ak, aSP, arelu, anp);
    rb0 = *(const float4*)(Bp + (size_t)(brow0 + br) * ldbp);
    rb1 = *(const float4*)(Bp + (size_t)(brow0 + br + 8) * ldbp);

    As[0][ak+0][ar] = cvt_tf32(ra0.x); As[0][ak+1][ar] = cvt_tf32(ra0.y);
    As[0][ak+2][ar] = cvt_tf32(ra0.z); As[0][ak+3][ar] = cvt_tf32(ra0.w);
    As[0][ak+0][ar+32] = cvt_tf32(ra1.x); As[0][ak+1][ar+32] = cvt_tf32(ra1.y);
    As[0][ak+2][ar+32] = cvt_tf32(ra1.z); As[0][ak+3][ar+32] = cvt_tf32(ra1.w);
    {
        uint4 u0 = make_uint4(cvt_tf32(rb0.x), cvt_tf32(rb0.y),
                              cvt_tf32(rb0.z), cvt_tf32(rb0.w));
        uint4 u1 = make_uint4(cvt_tf32(rb1.x), cvt_tf32(rb1.y),
                              cvt_tf32(rb1.z), cvt_tf32(rb1.w));
        *(uint4*)&Bs[0][br][bc]     = u0;
        *(uint4*)&Bs[0][br + 8][bc] = u1;
    }
    __syncthreads();

    float acc[2][4][4];
    #pragma unroll
    for (int mt = 0; mt < 2; mt++)
        #pragma unroll
        for (int nt = 0; nt < 4; nt++)
            #pragma unroll
            for (int r = 0; r < 4; r++) acc[mt][nt][r] = 0.f;

    int buf = 0;
    for (int k0 = 0; k0 < K; k0 += 16) {
        const bool more = (k0 + 16) < K;
        if (more) {
            int kc = k0 + 16 + ak;
            ra0 = ldA4(Ab + (size_t)ar * lda + kc, abias, azoff + kc, aSP, arelu, anp);
            ra1 = ldA4(Ab + (size_t)(ar + 32) * lda + kc, abias, azoff + kc, aSP, arelu, anp);
            rb0 = *(const float4*)(Bp + (size_t)(brow0 + k0 + 16 + br) * ldbp);
            rb1 = *(const float4*)(Bp + (size_t)(brow0 + k0 + 16 + br + 8) * ldbp);
        }
        #pragma unroll
        for (int kk = 0; kk < 16; kk += 8) {
            unsigned af[2][4], bf[4][2];
            #pragma unroll
            for (int mt = 0; mt < 2; mt++) {
                int m0 = wm + mt * 16 + g;
                af[mt][0] = As[buf][kk + t4][m0];
                af[mt][1] = As[buf][kk + t4][m0 + 8];
                af[mt][2] = As[buf][kk + 4 + t4][m0];
                af[mt][3] = As[buf][kk + 4 + t4][m0 + 8];
            }
            #pragma unroll
            for (int nt = 0; nt < 4; nt++) {
                int n0 = wn + nt * 8 + g;
                bf[nt][0] = Bs[buf][kk + t4][n0];
                bf[nt][1] = Bs[buf][kk + 4 + t4][n0];
            }
            #pragma unroll
            for (int mt = 0; mt < 2; mt++)
                #pragma unroll
                for (int nt = 0; nt < 4; nt++)
                    mma_tf32(acc[mt][nt], af[mt], bf[nt]);
        }
        if (more) {
            buf ^= 1;
            __syncthreads();
            As[buf][ak+0][ar] = cvt_tf32(ra0.x); As[buf][ak+1][ar] = cvt_tf32(ra0.y);
            As[buf][ak+2][ar] = cvt_tf32(ra0.z); As[buf][ak+3][ar] = cvt_tf32(ra0.w);
            As[buf][ak+0][ar+32] = cvt_tf32(ra1.x); As[buf][ak+1][ar+32] = cvt_tf32(ra1.y);
            As[buf][ak+2][ar+32] = cvt_tf32(ra1.z); As[buf][ak+3][ar+32] = cvt_tf32(ra1.w);
            uint4 u0 = make_uint4(cvt_tf32(rb0.x), cvt_tf32(rb0.y),
                                  cvt_tf32(rb0.z), cvt_tf32(rb0.w));
            uint4 u1 = make_uint4(cvt_tf32(rb1.x), cvt_tf32(rb1.y),
                                  cvt_tf32(rb1.z), cvt_tf32(rb1.w));
            *(uint4*)&Bs[buf][br][bc]     = u0;
            *(uint4*)&Bs[buf][br + 8][bc] = u1;
            __syncthreads();
        }
    }

    #pragma unroll
    for (int mt = 0; mt < 2; mt++) {
        int row0 = bm + wm + mt * 16 + g;
        #pragma unroll
        for (int nt = 0; nt < 4; nt++) {
            int col = bn + wn + nt * 8 + t4 * 2;
            float b0 = 0.f, b1 = 0.f;
            if (bias) { b0 = bias[col]; b1 = bias[col + 1]; }
            float2 v0 = make_float2(acc[mt][nt][0] + b0, acc[mt][nt][1] + b1);
            float2 v1 = make_float2(acc[mt][nt][2] + b0, acc[mt][nt][3] + b1);
            *(float2*)(C + (size_t)row0 * ldc + col)       = v0;
            *(float2*)(C + (size_t)(row0 + 8) * ldc + col) = v1;
        }
    }
}

// ---------------------------------------------------------------------------
// bias planes: att[h][i][j] = (p[i,j,:]·w_b[:,h] + b_b[h]) * sqrt(1/3)
// ---------------------------------------------------------------------------
__global__ void bias_kernel(const float* __restrict__ p,
                            const float* __restrict__ w_b,
                            const float* __restrict__ b_b,
                            float* __restrict__ att, int ibase)
{
    __shared__ float wbt[HDS][CP];
    __shared__ float bbs[HDS];
    const int tid = threadIdx.x;
    #pragma unroll
    for (int k = 0; k < 6; k++) {
        int e = tid + k * 256;
        int h = e / CP, c = e % CP;
        wbt[h][c] = w_b[c * HDS + h];
    }
    if (tid < HDS) bbs[tid] = b_b[tid];
    __syncthreads();

    const int gw = blockIdx.x * 8 + (tid >> 5);
    const int lane = tid & 31;
    const int i = ibase + (gw >> 4);
    const int j = ((gw & 15) << 5) + lane;

    float acc[HDS];
    #pragma unroll
    for (int h = 0; h < HDS; h++) acc[h] = 0.f;

    const float4* prow = (const float4*)(p + ((size_t)i * NN + j) * CP);
    #pragma unroll 4
    for (int c4 = 0; c4 < 32; c4++) {
        float4 pv = prow[c4];
        #pragma unroll
        for (int h = 0; h < HDS; h++) {
            float4 wv = ((const float4*)&wbt[h][0])[c4];
            acc[h] = fmaf(pv.x, wv.x,
                     fmaf(pv.y, wv.y,
                     fmaf(pv.z, wv.z,
                     fmaf(pv.w, wv.w, acc[h]))));
        }
    }
    #pragma unroll
    for (int h = 0; h < HDS; h++)
        att[((size_t)(h * NN) + i) * NN + j] = (acc[h] + bbs[h]) * SB;
}

// ---------------------------------------------------------------------------
// ov GEMM (att @ [v|vp], per-head) with fused postproc epilogue:
// writes o / rotated-op / norms directly into cat.  grid (1, 8, HDS).
// ---------------------------------------------------------------------------
__global__ void __launch_bounds__(128)
ovgemm_kernel(const float* __restrict__ att,
              const float* __restrict__ vpk,
              const float* __restrict__ rot,
              const float* __restrict__ trans,
              float* __restrict__ cat)
{
    const int h = blockIdx.z;
    const float* A = att + (size_t)h * NN * NN;
    const float* B = vpk + (size_t)h * NN * 64;

    __shared__ __align__(16) unsigned As[2][16][72];
    __shared__ __align__(16) unsigned Bs[2][16][72];
    __shared__ float sm[64][41];

    const int bm = blockIdx.y * 64;
    const int tid = threadIdx.x;
    const int lane = tid & 31, warp = tid >> 5;
    const int g = lane >> 2, t4 = lane & 3;
    const int wm = (warp >> 1) * 32, wn = (warp & 1) * 32;

    const int ar = tid >> 2, ak = (tid & 3) * 4;
    const int br = tid >> 4, bc = (tid & 15) * 4;

    const float* Ab = A + (size_t)bm * NN;

    float4 ra0, ra1, rb0, rb1;
    ra0 = *(const float4*)(Ab + (size_t)ar * NN + ak);
    ra1 = *(const float4*)(Ab + (size_t)(ar + 32) * NN + ak);
    rb0 = *(const float4*)(B + (size_t)br * 64 + bc);
    rb1 = *(const float4*)(B + (size_t)(br + 8) * 64 + bc);

    As[0][ak+0][ar] = cvt_tf32(ra0.x); As[0][ak+1][ar] = cvt_tf32(ra0.y);
    As[0][ak+2][ar] = cvt_tf32(ra0.z); As[0][ak+3][ar] = cvt_tf32(ra0.w);
    As[0][ak+0][ar+32] = cvt_tf32(ra1.x); As[0][ak+1][ar+32] = cvt_tf32(ra1.y);
    As[0][ak+2][ar+32] = cvt_tf32(ra1.z); As[0][ak+3][ar+32] = cvt_tf32(ra1.w);
    {
        uint4 u0 = make_uint4(cvt_tf32(rb0.x), cvt_tf32(rb0.y),
                              cvt_tf32(rb0.z), cvt_tf32(rb0.w));
        uint4 u1 = make_uint4(cvt_tf32(rb1.x), cvt_tf32(rb1.y),
                              cvt_tf32(rb1.z), cvt_tf32(rb1.w));
        *(uint4*)&Bs[0][br][bc]     = u0;
        *(uint4*)&Bs[0][br + 8][bc] = u1;
    }
    __syncthreads();

    float acc[2][4][4];
    #pragma unroll
    for (int mt = 0; mt < 2; mt++)
        #pragma unroll
        for (int nt = 0; nt < 4; nt++)
            #pragma unroll
            for (int r = 0; r < 4; r++) acc[mt][nt][r] = 0.f;

    int buf = 0;
    for (int k0 = 0; k0 < NN; k0 += 16) {
        const bool more = (k0 + 16) < NN;
        if (more) {
            ra0 = *(const float4*)(Ab + (size_t)ar * NN + k0 + 16 + ak);
            ra1 = *(const float4*)(Ab + (size_t)(ar + 32) * NN + k0 + 16 + ak);
            rb0 = *(const float4*)(B + (size_t)(k0 + 16 + br) * 64 + bc);
            rb1 = *(const float4*)(B + (size_t)(k0 + 16 + br + 8) * 64 + bc);
        }
        #pragma unroll
        for (int kk = 0; kk < 16; kk += 8) {
            unsigned af[2][4], bf[4][2];
            #pragma unroll
            for (int mt = 0; mt < 2; mt++) {
                int m0 = wm + mt * 16 + g;
                af[mt][0] = As[buf][kk + t4][m0];
                af[mt][1] = As[buf][kk + t4][m0 + 8];
                af[mt][2] = As[buf][kk + 4 + t4][m0];
                af[mt][3] = As[buf][kk + 4 + t4][m0 + 8];
            }
            #pragma unroll
            for (int nt = 0; nt < 4; nt++) {
                int n0 = wn + nt * 8 + g;
                bf[nt][0] = Bs[buf][kk + t4][n0];
                bf[nt][1] = Bs[buf][kk + 4 + t4][n0];
            }
            #pragma unroll
            for (int mt = 0; mt < 2; mt++)
                #pragma unroll
                for (int nt = 0; nt < 4; nt++)
                    mma_tf32(acc[mt][nt], af[mt], bf[nt]);
        }
        if (more) {
            buf ^= 1;
            __syncthreads();
            As[buf][ak+0][ar] = cvt_tf32(ra0.x); As[buf][ak+1][ar] = cvt_tf32(ra0.y);
            As[buf][ak+2][ar] = cvt_tf32(ra0.z); As[buf][ak+3][ar] = cvt_tf32(ra0.w);
            As[buf][ak+0][ar+32] = cvt_tf32(ra1.x); As[buf][ak+1][ar+32] = cvt_tf32(ra1.y);
            As[buf][ak+2][ar+32] = cvt_tf32(ra1.z); As[buf][ak+3][ar+32] = cvt_tf32(ra1.w);
            uint4 u0 = make_uint4(cvt_tf32(rb0.x), cvt_tf32(rb0.y),
                                  cvt_tf32(rb0.z), cvt_tf32(rb0.w));
            uint4 u1 = make_uint4(cvt_tf32(rb1.x), cvt_tf32(rb1.y),
                                  cvt_tf32(rb1.z), cvt_tf32(rb1.w));
            *(uint4*)&Bs[buf][br][bc]     = u0;
            *(uint4*)&Bs[buf][br + 8][bc] = u1;
            __syncthreads();
        }
    }

    #pragma unroll
    for (int mt = 0; mt < 2; mt++) {
        int r0 = wm + mt * 16 + g;
        #pragma unroll
        for (int nt = 0; nt < 4; nt++) {
            int col = wn + nt * 8 + t4 * 2;
            if (col < 40) {
                sm[r0][col]       = acc[mt][nt][0];
                sm[r0][col + 1]   = acc[mt][nt][1];
                sm[r0 + 8][col]     = acc[mt][nt][2];
                sm[r0 + 8][col + 1] = acc[mt][nt][3];
            }
        }
    }
    __syncthreads();

    #pragma unroll
    for (int l = 0; l < 8; l++) {
        int e = tid + l * 128;
        int r = e >> 4, c = e & 15;
        cat[(size_t)(bm + r) * 2112 + h * 16 + c] = sm[r][c];
    }
    #pragma unroll
    for (int l = 0; l < 4; l++) {
        int e = tid + l * 128;
        int r = e >> 3, pp = e & 7;
        int i = bm + r;
        float vx = sm[r][16 + pp*3 + 0] - trans[i*3 + 0];
        float vy = sm[r][16 + pp*3 + 1] - trans[i*3 + 1];
        float vz = sm[r][16 + pp*3 + 2] - trans[i*3 + 2];
        const float* R = rot + i * 9;
        float ox = R[0]*vx + R[3]*vy + R[6]*vz;
        float oy = R[1]*vx + R[4]*vy + R[7]*vz;
        float oz = R[2]*vx + R[5]*vy + R[8]*vz;
        float* ci = cat + (size_t)i * 2112;
        ci[192 + h*24 + pp*3 + 0] = ox;
        ci[192 + h*24 + pp*3 + 1] = oy;
        ci[192 + h*24 + pp*3 + 2] = oz;
        ci[480 + h*8 + pp] = sqrtf(ox*ox + oy*oy + oz*oz + 1e-8f);
    }
}

// ---------------------------------------------------------------------------
// o_pair via tensor cores: per-i block computes (16x512)@(512x128).
// ibase: starting residue (for i-split across streams).
// ---------------------------------------------------------------------------
extern __shared__ unsigned dyn_smem[];
__global__ void __launch_bounds__(128)
opair_tc_kernel(const float* __restrict__ att,
                const float* __restrict__ p,
                float* __restrict__ cat, int ibase)
{
    const int i = ibase + blockIdx.x;
    unsigned* As = dyn_smem;                 // [j][h] stride 17
    unsigned* Bs = dyn_smem + 512 * 17;      // [jj][c] stride 132
    const int tid = threadIdx.x;

    for (int idx = tid; idx < HDS * NN; idx += 128) {
        int j = idx & 511, h = idx >> 9;
        As[j * 17 + h] = cvt_tf32(att[((size_t)(h * NN) + i) * NN + j]);
    }
    for (int idx = tid; idx < 4 * NN; idx += 128) {
        int j = idx & 511, h = 12 + (idx >> 9);
        As[j * 17 + h] = 0u;
    }

    const int lane = tid & 31, warp = tid >> 5;
    const int g = lane >> 2, t4 = lane & 3;
    const int wn = warp * 32;

    float acc[4][4];
    #pragma unroll
    for (int nt = 0; nt < 4; nt++)
        #pragma unroll
        for (int r = 0; r < 4; r++) acc[nt][r] = 0.f;

    const float4* pi4 = (const float4*)(p + (size_t)i * NN * CP);

    for (int j0 = 0; j0 < NN; j0 += 64) {
        __syncthreads();
        #pragma unroll
        for (int l = 0; l < 16; l++) {
            int e = tid + l * 128;
            int jj = e >> 5, c4 = e & 31;
            float4 v = pi4[(size_t)(j0 + jj) * 32 + c4];
            uint4 u = make_uint4(cvt_tf32(v.x), cvt_tf32(v.y),
                                 cvt_tf32(v.z), cvt_tf32(v.w));
            *(uint4*)&Bs[jj * 132 + c4 * 4] = u;
        }
        __syncthreads();
        #pragma unroll
        for (int ks = 0; ks < 8; ks++) {
            unsigned af[4];
            int kg = (j0 + ks * 8 + t4) * 17;
            int kg4 = (j0 + ks * 8 + 4 + t4) * 17;
            af[0] = As[kg + g];
            af[1] = As[kg + g + 8];
            af[2] = As[kg4 + g];
            af[3] = As[kg4 + g + 8];
            #pragma unroll
            for (int nt = 0; nt < 4; nt++) {
                unsigned bf[2];
                int n0 = wn + nt * 8 + g;
                bf[0] = Bs[(ks * 8 + t4) * 132 + n0];
                bf[1] = Bs[(ks * 8 + 4 + t4) * 132 + n0];
                mma_tf32(acc[nt], af, bf);
            }
        }
    }

    float* dst = cat + (size_t)i * 2112 + 576;
    #pragma unroll
    for (int nt = 0; nt < 4; nt++) {
        int col = wn + nt * 8 + t4 * 2;
        dst[g * 128 + col]     = acc[nt][0];
        dst[g * 128 + col + 1] = acc[nt][1];
        if (g + 8 < HDS) {
            dst[(g + 8) * 128 + col]     = acc[nt][2];
            dst[(g + 8) * 128 + col + 1] = acc[nt][3];
        }
    }
}

// ---------------------------------------------------------------------------
// Fused proj split-K reduce (4 partials) + bias + rotate + repack.
// ---------------------------------------------------------------------------
__global__ void rotpack_kernel(const float* __restrict__ ppart,
                               const float* __restrict__ b_q,
                               const float* __restrict__ b_kv,
                               const float* __restrict__ b_qp,
                               const float* __restrict__ b_kvp,
                               const float* __restrict__ rot,
                               const float* __restrict__ trans,
                               float* __restrict__ proj,
                               float* __restrict__ kpack,
                               float* __restrict__ kppack,
                               float* __restrict__ vpack)
{
    const long long SP = (long long)NN * LDP;
    const int S0 = NN * 48;
    const int S1 = S0 + HDS * NN * 4;
    const int S2 = S1 + HDS * NN * 4;
    const int S3 = S2 + HDS * NN * 4;
    const int S4 = S3 + HDS * NN * 8;
    const int S5 = S4 + NN * 48;
    int idx = blockIdx.x * blockDim.x + threadIdx.x;

    if (idx < S0) {
        int j = idx / 48, c = (idx % 48) * 4;
        const float* p0 = ppart + (size_t)j * LDP + c;
        float4 a = *(const float4*)p0;
        float4 b1 = *(const float4*)(p0 + SP);
        float4 b2 = *(const float4*)(p0 + 2 * SP);
        float4 b3 = *(const float4*)(p0 + 3 * SP);
        float4 bb = *(const float4*)(b_q + c);
        *(float4*)(proj + (size_t)j * LDP + c) =
            make_float4(a.x+b1.x+b2.x+b3.x+bb.x, a.y+b1.y+b2.y+b3.y+bb.y,
                        a.z+b1.z+b2.z+b3.z+bb.z, a.w+b1.w+b2.w+b3.w+bb.w);
    } else if (idx < S1) {
        int t = idx - S0;
        int c = (t & 3) * 4, j = (t >> 2) & 511, h = t >> 11;
        int col = OFF_KV + h * 32 + c;
        const float* p0 = ppart + (size_t)j * LDP + col;
        float4 a = *(const float4*)p0;
        float4 b1 = *(const float4*)(p0 + SP);
        float4 b2 = *(const float4*)(p0 + 2 * SP);
        float4 b3 = *(const float4*)(p0 + 3 * SP);
        float4 bb = *(const float4*)(b_kv + h * 32 + c);
        *(float4*)(kpack + (((size_t)h * NN) + j) * 16 + c) =
            make_float4(a.x+b1.x+b2.x+b3.x+bb.x, a.y+b1.y+b2.y+b3.y+bb.y,
                        a.z+b1.z+b2.z+b3.z+bb.z, a.w+b1.w+b2.w+b3.w+bb.w);
    } else if (idx < S2) {
        int t = idx - S1;
        int c = (t & 3) * 4, j = (t >> 2) & 511, h = t >> 11;
        int col = OFF_KV + h * 32 + 16 + c;
        const float* p0 = ppart + (size_t)j * LDP + col;
        float4 a = *(const float4*)p0;
        float4 b1 = *(const float4*)(p0 + SP);
        float4 b2 = *(const float4*)(p0 + 2 * SP);
        float4 b3 = *(const float4*)(p0 + 3 * SP);
        float4 bb = *(const float4*)(b_kv + h * 32 + 16 + c);
        *(float4*)(vpack + (((size_t)h * NN) + j) * 64 + c) =
            make_float4(a.x+b1.x+b2.x+b3.x+bb.x, a.y+b1.y+b2.y+b3.y+bb.y,
                        a.z+b1.z+b2.z+b3.z+bb.z, a.w+b1.w+b2.w+b3.w+bb.w);
    } else if (idx < S4) {
        int t = idx - S2;
        int pp, j, h;
        float* dst;
        if (t < HDS * NN * 4) {
            pp = t & 3; j = (t >> 2) & 511; h = t >> 11;
            dst = kppack + (((size_t)h * NN) + j) * 12 + pp * 3;
        } else {
            t -= HDS * NN * 4;
            int vp = t & 7; j = (t >> 3) & 511; h = t >> 12;
            pp = 4 + vp;
            dst = vpack + (((size_t)h * NN) + j) * 64 + 16 + vp * 3;
        }
        int col = OFF_KVP + h * 36 + pp * 3;
        int lcol = h * 36 + pp * 3;
        const float* p0 = ppart + (size_t)j * LDP + col;
        float x = p0[0] + p0[SP+0] + p0[2*SP+0] + p0[3*SP+0] + b_kvp[lcol + 0];
        float y = p0[1] + p0[SP+1] + p0[2*SP+1] + p0[3*SP+1] + b_kvp[lcol + 1];
        float z = p0[2] + p0[SP+2] + p0[2*SP+2] + p0[3*SP+2] + b_kvp[lcol + 2];
        const float* R = rot + j * 9;
        const float* tr = trans + j * 3;
        dst[0] = R[0]*x + R[1]*y + R[2]*z + tr[0];
        dst[1] = R[3]*x + R[4]*y + R[5]*z + tr[1];
        dst[2] = R[6]*x + R[7]*y + R[8]*z + tr[2];
    } else if (idx < S5) {
        int t = idx - S4;
        int pt = t % 48, j = t / 48;
        int col = OFF_QP + pt * 3;
        const float* p0 = ppart + (size_t)j * LDP + col;
        float x = p0[0] + p0[SP+0] + p0[2*SP+0] + p0[3*SP+0] + b_qp[pt*3 + 0];
        float y = p0[1] + p0[SP+1] + p0[2*SP+1] + p0[3*SP+1] + b_qp[pt*3 + 1];
        float z = p0[2] + p0[SP+2] + p0[2*SP+2] + p0[3*SP+2] + b_qp[pt*3 + 2];
        const float* R = rot + j * 9;
        const float* tr = trans + j * 3;
        float* pv = proj + (size_t)j * LDP + col;
        pv[0] = R[0]*x + R[1]*y + R[2]*z + tr[0];
        pv[1] = R[3]*x + R[4]*y + R[5]*z + tr[1];
        pv[2] = R[6]*x + R[7]*y + R[8]*z + tr[2];
    }
}

// ---------------------------------------------------------------------------
// Fused logits + softmax.  Block = (i-tile of 8, head h).  256 threads.
// One-shot full staging of k/kp/mask in dynamic smem (2 syncs total).
// ---------------------------------------------------------------------------
__global__ void __launch_bounds__(256)
logits_softmax_kernel(const float* __restrict__ proj,
                      const float* __restrict__ kpack,
                      const float* __restrict__ kppack,
                      const float* __restrict__ mask,
                      const float* __restrict__ head_w,
                      float* __restrict__ att, int ibase)
{
    const int i0 = ibase + blockIdx.x * 8, h = blockIdx.y;
    const int tid = threadIdx.x;

    float* lsm   = (float*)dyn_smem;
    float* kt    = lsm;                           // [512][17]
    float* kpt   = kt + 512 * 17;                 // [512][13]
    float* att_s = kpt + 512 * 13;                // [8][512]
    float* q_s   = att_s + 8 * 512;               // [8][17]
    float* qp_s  = q_s + 8 * 17;                  // [8][13]
    float* m_j   = qp_s + 8 * 13;                 // [512]
    float* m_i   = m_j + 512;                     // [8]
    float* sh_hw = m_i + 8;                       // [1]

    const float* kb  = kpack  + (size_t)(h * NN) * 16;
    const float* kpb = kppack + (size_t)(h * NN) * 12;

    if (tid < 128) {
        int il = tid >> 4, c = tid & 15;
        q_s[il * 17 + c] = proj[(size_t)(i0 + il) * LDP + OFF_Q + h * 16 + c];
    } else if (tid < 224) {
        int e = tid - 128;
        int il = e / 12, c = e % 12;
        qp_s[il * 13 + c] = proj[(size_t)(i0 + il) * LDP + OFF_QP + h * 12 + c];
    } else if (tid < 232) {
        m_i[tid - 224] = mask[i0 + (tid - 224)];
    } else if (tid == 232) {
        float w = head_w[h];
        float sp = fmaxf(w, 0.f) + log1pf(expf(-fabsf(w)));
        sh_hw[0] = sp * SHW;
    }
    #pragma unroll
    for (int e = tid; e < 512 * 16; e += 256) {
        int r = e >> 4, c = e & 15;
        kt[r * 17 + c] = kb[e];
    }
    #pragma unroll
    for (int e = tid; e < 512 * 12; e += 256) {
        int r = e / 12, c = e % 12;
        kpt[r * 13 + c] = kpb[e];
    }
    if (tid < 256) {
        m_j[tid] = mask[tid];
        m_j[tid + 256] = mask[tid + 256];
    }
    __syncthreads();

    const int jl = tid & 63, ig = tid >> 6;
    const float hw = sh_hw[0];

    #pragma unroll
    for (int t = 0; t < 8; t++) {
        int j = jl + t * 64;
        float mj = m_j[j];
        #pragma unroll
        for (int ii = 0; ii < 2; ii++) {
            int il = ig * 2 + ii;
            float qk = 0.f;
            #pragma unroll
            for (int c = 0; c < 16; c++)
                qk = fmaf(q_s[il * 17 + c], kt[j * 17 + c], qk);
            float d2 = 0.f;
            #pragma unroll
            for (int d = 0; d < 12; d++) {
                float dd = qp_s[il * 13 + d] - kpt[j * 13 + d];
                d2 = fmaf(dd, dd, d2);
            }
            float bias = att[((size_t)(h * NN) + i0 + il) * NN + j];
            att_s[il * 512 + j] = qk * SQK + bias - 0.5f * hw * d2
                                + (m_i[il] * mj - 1.0f) * 100000.0f;
        }
    }
    __syncthreads();

    const int w = tid >> 5, lane = tid & 31;
    float vals[16];
    float vmax = -1e30f;
    #pragma unroll
    for (int k = 0; k < 16; k++) {
        vals[k] = att_s[w * 512 + lane + 32 * k];
        vmax = fmaxf(vmax, vals[k]);
    }
    #pragma unroll
    for (int o = 16; o > 0; o >>= 1)
        vmax = fmaxf(vmax, __shfl_xor_sync(0xffffffffu, vmax, o));
    float sum = 0.f;
    #pragma unroll
    for (int k = 0; k < 16; k++) { vals[k] = expf(vals[k] - vmax); sum += vals[k]; }
    #pragma unroll
    for (int o = 16; o > 0; o >>= 1)
        sum += __shfl_xor_sync(0xffffffffu, sum, o);
    float inv = 1.0f / sum;
    float* arow = att + ((size_t)(h * NN) + i0 + w) * NN;
    #pragma unroll
    for (int k = 0; k < 16; k++)
        arow[lane + 32 * k] = vals[k] * inv;
}

// ---------------------------------------------------------------------------
// 6-way split-K reduce + bias + residual + LayerNorm.  Block/row, 128 thr.
// ---------------------------------------------------------------------------
__global__ void reduce_ln_kernel(const float* __restrict__ part,
                                 const float* __restrict__ bias,
                                 const float* __restrict__ res,
                                 const float* __restrict__ g,
                                 const float* __restrict__ b,
                                 float* __restrict__ y)
{
    __shared__ float rs[128], rs2[128];
    const int i = blockIdx.x, tid = threadIdx.x;
    const size_t SP = (size_t)NN * CS;
    float v[3];
    float sm = 0.f, sm2 = 0.f;
    #pragma unroll
    for (int k = 0; k < 3; k++) {
        int c = tid + k * 128;
        size_t o = (size_t)i * CS + c;
        float x = bias[c] + res[o];
        #pragma unroll
        for (int sl = 0; sl < 6; sl++) x += part[sl * SP + o];
        v[k] = x;
        sm += x; sm2 += x * x;
    }
    rs[tid] = sm; rs2[tid] = sm2;
    __syncthreads();
    for (int st = 64; st > 0; st >>= 1) {
        if (tid < st) { rs[tid] += rs[tid + st]; rs2[tid] += rs2[tid + st]; }
        __syncthreads();
    }
    float mean = rs[0] * (1.0f / CS);
    float var  = rs2[0] * (1.0f / CS) - mean * mean;
    float inv  = rsqrtf(var + 1e-5f);
    #pragma unroll
    for (int k = 0; k < 3; k++) {
        int c = tid + k * 128;
        y[(size_t)i * CS + c] = (v[k] - mean) * inv * g[c] + b[c];
    }
}

// ---------------------------------------------------------------------------
// Fused: 6-way reduce + bias + residual + LayerNorm2 + backbone projection
// + quaternion frame update.  Block per row, 128 threads.
// ---------------------------------------------------------------------------
__global__ void lnbb_kernel(const float* __restrict__ part,
                            const float* __restrict__ bias,
                            const float* __restrict__ res,
                            const float* __restrict__ g,
                            const float* __restrict__ b,
                            const float* __restrict__ bb_w,
                            const float* __restrict__ bb_b,
                            const float* __restrict__ rot,
                            const float* __restrict__ trans,
                            float* __restrict__ out)
{
    __shared__ float rs[128], rs2[128], ys[CS], wsm[CS * 6], u[6];
    const int i = blockIdx.x, tid = threadIdx.x;
    const size_t SP = (size_t)NN * CS;

    #pragma unroll
    for (int k = 0; k < 18; k++) wsm[tid + k * 128] = bb_w[tid + k * 128];

    float v[3];
    float sm = 0.f, sm2 = 0.f;
    #pragma unroll
    for (int k = 0; k < 3; k++) {
        int c = tid + k * 128;
        size_t o = (size_t)i * CS + c;
        float x = bias[c] + res[o];
        #pragma unroll
        for (int sl = 0; sl < 6; sl++) x += part[sl * SP + o];
        v[k] = x;
        sm += x; sm2 += x * x;
    }
    rs[tid] = sm; rs2[tid] = sm2;
    __syncthreads();
    for (int st = 64; st > 0; st >>= 1) {
        if (tid < st) { rs[tid] += rs[tid + st]; rs2[tid] += rs2[tid + st]; }
        __syncthreads();
    }
    float mean = rs[0] * (1.0f / CS);
    float var  = rs2[0] * (1.0f / CS) - mean * mean;
    float inv  = rsqrtf(var + 1e-5f);
    #pragma unroll
    for (int k = 0; k < 3; k++) {
        int c = tid + k * 128;
        float yv = (v[k] - mean) * inv * g[c] + b[c];
        ys[c] = yv;
        out[(size_t)i * CS + c] = yv;
    }
    __syncthreads();

    if (tid < 32) {
        #pragma unroll
        for (int o = 0; o < 6; o++) {
            float sum = 0.f;
            for (int c = tid; c < CS; c += 32)
                sum = fmaf(ys[c], wsm[c * 6 + o], sum);
            #pragma unroll
            for (int off = 16; off > 0; off >>= 1)
                sum += __shfl_xor_sync(0xffffffffu, sum, off);
            if (tid == 0) u[o] = sum + bb_b[o];
        }
        if (tid == 0) {
            float bx = u[0], by = u[1], bz = u[2];
            float qinv = rsqrtf(1.f + bx*bx + by*by + bz*bz);
            float qw = qinv, x = bx * qinv, y = by * qinv, z = bz * qinv;
            float Ru[9] = {
                1 - 2*(y*y + z*z), 2*(x*y - qw*z),    2*(x*z + qw*y),
                2*(x*y + qw*z),    1 - 2*(x*x + z*z), 2*(y*z - qw*x),
                2*(x*z - qw*y),    2*(y*z + qw*x),    1 - 2*(x*x + y*y)};
            const float* R = rot + i * 9;
            float* ro = out + NN * CS + i * 9;
            #pragma unroll
            for (int r = 0; r < 3; r++)
                #pragma unroll
                for (int c = 0; c < 3; c++)
                    ro[r*3+c] = R[r*3+0]*Ru[0*3+c] + R[r*3+1]*Ru[1*3+c]
                              + R[r*3+2]*Ru[2*3+c];
            float tx = u[3], ty = u[4], tz = u[5];
            float* to = out + NN * CS + NN * 9 + i * 3;
            #pragma unroll
            for (int r = 0; r < 3; r++)
                to[r] = R[r*3+0]*tx + R[r*3+1]*ty + R[r*3+2]*tz + trans[i*3+r];
        }
    }
}

// ---------------------------------------------------------------------------
static cudaStream_t g_s1 = nullptr;
static cudaEvent_t  g_ev0, g_ev1a, g_ev1b, g_ev2, g_ev3a, g_ev3b;

extern "C" void kernel_launch(void* const* d_in, const int* in_sizes, int n_in,
                              void* d_out, int out_size)
{
    if (!g_s1) {
        cudaStreamCreateWithFlags(&g_s1, cudaStreamNonBlocking);
        cudaEventCreateWithFlags(&g_ev0,  cudaEventDisableTiming);
        cudaEventCreateWithFlags(&g_ev1a, cudaEventDisableTiming);
        cudaEventCreateWithFlags(&g_ev1b, cudaEventDisableTiming);
        cudaEventCreateWithFlags(&g_ev2,  cudaEventDisableTiming);
        cudaEventCreateWithFlags(&g_ev3a, cudaEventDisableTiming);
        cudaEventCreateWithFlags(&g_ev3b, cudaEventDisableTiming);
        cudaFuncSetAttribute(opair_tc_kernel,
                             cudaFuncAttributeMaxDynamicSharedMemorySize,
                             OPAIR_SMEM);
        cudaFuncSetAttribute(logits_softmax_kernel,
                             cudaFuncAttributeMaxDynamicSharedMemorySize,
                             LOGITS_SMEM);
    }

    const float* s      = (const float*)d_in[0];
    const float* p      = (const float*)d_in[1];
    const float* rot    = (const float*)d_in[2];
    const float* trans  = (const float*)d_in[3];
    const float* mask   = (const float*)d_in[4];
    const float* w_q    = (const float*)d_in[5];
    const float* b_q    = (const float*)d_in[6];
    const float* w_kv   = (const float*)d_in[7];
    const float* b_kv   = (const float*)d_in[8];
    const float* w_qp   = (const float*)d_in[9];
    const float* b_qp   = (const float*)d_in[10];
    const float* w_kvp  = (const float*)d_in[11];
    const float* b_kvp  = (const float*)d_in[12];
    const float* w_b    = (const float*)d_in[13];
    const float* b_b    = (const float*)d_in[14];
    const float* head_w = (const float*)d_in[15];
    const float* w_o    = (const float*)d_in[16];
    const float* b_o    = (const float*)d_in[17];
    const float* ln1_g  = (const float*)d_in[18];
    const float* ln1_b  = (const float*)d_in[19];
    const float* tw1    = (const float*)d_in[20];
    const float* tb1    = (const float*)d_in[21];
    const float* tw2    = (const float*)d_in[22];
    const float* tb2    = (const float*)d_in[23];
    const float* tw3    = (const float*)d_in[24];
    const float* tb3    = (const float*)d_in[25];
    const float* ln2_g  = (const float*)d_in[26];
    const float* ln2_b  = (const float*)d_in[27];
    const float* bb_w   = (const float*)d_in[28];
    const float* bb_b   = (const float*)d_in[29];
    float* out = (float*)d_out;

    float *proj, *ppart, *kpk, *kppk, *vpk, *a_, *cat_, *part, *partB, *x2;
    cudaGetSymbolAddress((void**)&proj, g_proj);
    cudaGetSymbolAddress((void**)&ppart, g_ppart);
    cudaGetSymbolAddress((void**)&kpk,  g_kpack);
    cudaGetSymbolAddress((void**)&kppk, g_kppack);
    cudaGetSymbolAddress((void**)&vpk,  g_vpack);
    cudaGetSymbolAddress((void**)&a_,   g_att);
    cudaGetSymbolAddress((void**)&cat_, g_cat);
    cudaGetSymbolAddress((void**)&part, g_part);
    cudaGetSymbolAddress((void**)&partB, g_partB);
    cudaGetSymbolAddress((void**)&x2,   g_x2);

    const long long SPC = (long long)NN * CS;

    // ---- fork: bias planes on side stream, split into two i-halves --------
    cudaEventRecord(g_ev0, 0);
    cudaStreamWaitEvent(g_s1, g_ev0, 0);
    bias_kernel<<<512, 256, 0, g_s1>>>(p, w_b, b_b, a_, 0);
    cudaEventRecord(g_ev1a, g_s1);
    bias_kernel<<<512, 256, 0, g_s1>>>(p, w_b, b_b, a_, 256);
    cudaEventRecord(g_ev1b, g_s1);

    // ---- main: projections (split-K 4, B read directly from weights) ------
    gemm64_kernel<<<dim3(LDP / 64, 8, 4), 128>>>(
        s, CS, 0, 96,
        w_q, 0, 0, 96,
        w_kv, w_qp, w_kvp, 1,
        nullptr,
        ppart, LDP, 0, (long long)NN * LDP,
        96, 4, nullptr, 0, 0, 0, 0);
    {
        const int TOT = NN*48 + HDS*NN*4*3 + HDS*NN*8 + NN*48;
        rotpack_kernel<<<(TOT + 255) / 256, 256>>>(
            ppart, b_q, b_kv, b_qp, b_kvp, rot, trans,
            proj, kpk, kppk, vpk);
    }

    // pipelined logits: first i-half as soon as bias half 1 is done
    cudaStreamWaitEvent(0, g_ev1a, 0);
    logits_softmax_kernel<<<dim3(32, HDS), 256, LOGITS_SMEM>>>(
        proj, kpk, kppk, mask, head_w, a_, 0);
    cudaStreamWaitEvent(0, g_ev1b, 0);
    logits_softmax_kernel<<<dim3(32, HDS), 256, LOGITS_SMEM>>>(
        proj, kpk, kppk, mask, head_w, a_, 256);

    // ---- fork: opair (two i-halves) on side stream -------------------------
    cudaEventRecord(g_ev2, 0);
    cudaStreamWaitEvent(g_s1, g_ev2, 0);
    opair_tc_kernel<<<256, 128, OPAIR_SMEM, g_s1>>>(a_, p, cat_, 0);
    cudaEventRecord(g_ev3a, g_s1);
    opair_tc_kernel<<<256, 128, OPAIR_SMEM, g_s1>>>(a_, p, cat_, 256);
    cudaEventRecord(g_ev3b, g_s1);

    // main: fused ov GEMM + postproc, then w_o low-K (slots 0..1)
    ovgemm_kernel<<<dim3(1, 8, HDS), 128>>>(a_, vpk, rot, trans, cat_);
    gemm64_kernel<<<dim3(6, 8, 2), 128>>>(
        cat_, 2112, 0, 288,
        w_o, CS, 0, (long long)288 * CS,
        nullptr, nullptr, nullptr, 0,
        nullptr,
        part, CS, 0, SPC,
        288, 2, nullptr, 0, 0, 0, 0);

    // w_o high-K (opair cols), pipelined by M-half behind opair halves
    cudaStreamWaitEvent(0, g_ev3a, 0);
    gemm64_kernel<<<dim3(6, 4, 4), 128>>>(
        cat_ + 576, 2112, 0, 384,
        w_o + 576 * CS, CS, 0, (long long)384 * CS,
        nullptr, nullptr, nullptr, 0,
        nullptr,
        part + 2 * SPC, CS, 0, SPC,
        384, 4, nullptr, 0, 0, 0, 0);
    cudaStreamWaitEvent(0, g_ev3b, 0);
    gemm64_kernel<<<dim3(6, 4, 4), 128>>>(
        cat_ + 576 + (size_t)256 * 2112, 2112, 0, 384,
        w_o + 576 * CS, CS, 0, (long long)384 * CS,
        nullptr, nullptr, nullptr, 0,
        nullptr,
        part + 2 * SPC + (size_t)256 * CS, CS, 0, SPC,
        384, 4, nullptr, 0, 0, 0, 0);

    // ---- reduce(6) + residual + LN1 ----------------------------------------
    reduce_ln_kernel<<<NN, 128>>>(part, b_o, s, ln1_g, ln1_b, x2);

    // ---- transition MLP: split-K 6, reduces fused into next GEMM ----------
    gemm64_kernel<<<dim3(6, 8, 6), 128>>>(
        x2, CS, 0, 64,
        tw1, CS, 0, (long long)64 * CS,
        nullptr, nullptr, nullptr, 0,
        nullptr,
        partB, CS, 0, SPC,
        64, 6, nullptr, 0, 0, 0, 0);
    gemm64_kernel<<<dim3(6, 8, 6), 128>>>(
        partB, CS, 0, 64,
        tw2, CS, 0, (long long)64 * CS,
        nullptr, nullptr, nullptr, 0,
        nullptr,
        part, CS, 0, SPC,
        64, 6, tb1, SPC, 64, 1, 6);
    gemm64_kernel<<<dim3(6, 8, 6), 128>>>(
        part, CS, 0, 64,
        tw3, CS, 0, (long long)64 * CS,
        nullptr, nullptr, nullptr, 0,
        nullptr,
        partB, CS, 0, SPC,
        64, 6, tb2, SPC, 64, 1, 6);

    // ---- reduce(6) + residual + LN2 + backbone update ----------------------
    lnbb_kernel<<<NN, 128>>>(partB, tb3, x2, ln2_g, ln2_b,
                             bb_w, bb_b, rot, trans, out);
}